// round 1
// baseline (speedup 1.0000x reference)
#include <cuda_runtime.h>
#include <math.h>

#define BN 4
#define NX 4096
#define NYP 8192
#define GP 4096
#define CN 32
#define SN 16

// ---------------- scratch (static device globals; no allocation) ----------------
__device__ __align__(16) float  g_xe[BN*GP];
__device__ __align__(16) float  g_le[BN*GP*2];
__device__ __align__(16) float  g_h[2][BN*CN*GP];
__device__ __align__(16) float2 g_xf[BN*CN*16*8];
__device__ __align__(16) float2 g_of[BN*CN*16*8];
__device__ __align__(16) float2 g_Fm[BN*CN*17*9];
__device__ __align__(16) float2 g_img[BN*SN*17*17];
__device__ __align__(16) float  g_mn[BN*SN*2];
__device__ __align__(16) float  g_mx[BN*SN*2];
__device__ __align__(16) float  g_hl[BN*GP];
__device__ __align__(16) float  g_nu[BN*NYP];

__device__ __forceinline__ float wred(float v){
    #pragma unroll
    for (int o = 16; o; o >>= 1) v += __shfl_down_sync(0xffffffffu, v, o);
    return v;
}
__device__ __forceinline__ float2 cmul(float2 a, float2 b){
    return make_float2(a.x*b.x - a.y*b.y, a.x*b.y + a.y*b.x);
}
__device__ __forceinline__ float gelu(float v){
    return 0.5f*v*(1.0f + erff(v*0.70710678118654752f));
}

// ---------------- xe = W_embed1 @ x  (per-batch matvec) ----------------
__global__ void k_embed1(const float* __restrict__ W, const float* __restrict__ x,
                         const float* __restrict__ bias){
    int warp = (blockIdx.x*blockDim.x + threadIdx.x) >> 5;
    int lane = threadIdx.x & 31;
    if (warp >= GP) return;
    const float4* Wr = reinterpret_cast<const float4*>(W + (size_t)warp*NX);
    float acc[4] = {0,0,0,0};
    for (int i = lane; i < NX/4; i += 32){
        float4 w = __ldg(Wr + i);
        #pragma unroll
        for (int b = 0; b < 4; b++){
            float4 xv = __ldg(reinterpret_cast<const float4*>(x + (size_t)b*NX) + i);
            acc[b] += w.x*xv.x + w.y*xv.y + w.z*xv.z + w.w*xv.w;
        }
    }
    #pragma unroll
    for (int b = 0; b < 4; b++) acc[b] = wred(acc[b]);
    if (lane == 0){
        float bv = bias[warp];
        #pragma unroll
        for (int b = 0; b < 4; b++) g_xe[(size_t)b*GP + warp] = acc[b] + bv;
    }
}

// ---------------- le = W_embed2 @ loc ----------------
__global__ void k_embed2(const float* __restrict__ W, const float* __restrict__ loc,
                         const float* __restrict__ bias){
    int warp = (blockIdx.x*blockDim.x + threadIdx.x) >> 5;
    int lane = threadIdx.x & 31;
    if (warp >= GP) return;
    const float4* Wr = reinterpret_cast<const float4*>(W + (size_t)warp*NYP);
    float a0[4] = {0,0,0,0}, a1[4] = {0,0,0,0};
    for (int i = lane; i < NYP/4; i += 32){
        float4 w = __ldg(Wr + i);
        #pragma unroll
        for (int b = 0; b < 4; b++){
            const float4* lp = reinterpret_cast<const float4*>(loc + (size_t)b*NYP*2);
            float4 p01 = __ldg(lp + 2*i);
            float4 p23 = __ldg(lp + 2*i + 1);
            a0[b] += w.x*p01.x + w.y*p01.z + w.z*p23.x + w.w*p23.z;
            a1[b] += w.x*p01.y + w.y*p01.w + w.z*p23.y + w.w*p23.w;
        }
    }
    #pragma unroll
    for (int b = 0; b < 4; b++){ a0[b] = wred(a0[b]); a1[b] = wred(a1[b]); }
    if (lane == 0){
        float bv = bias[warp];
        #pragma unroll
        for (int b = 0; b < 4; b++){
            g_le[((size_t)b*GP + warp)*2 + 0] = a0[b] + bv;
            g_le[((size_t)b*GP + warp)*2 + 1] = a1[b] + bv;
        }
    }
}

// ---------------- fc0: (xe,le0,le1) -> 32 channels ----------------
__global__ void k_fc0(const float* __restrict__ Wf, const float* __restrict__ bf){
    int idx = blockIdx.x*blockDim.x + threadIdx.x;
    if (idx >= BN*GP) return;
    int b = idx >> 12, g = idx & (GP-1);
    float i0 = g_xe[idx];
    float i1 = g_le[(size_t)idx*2];
    float i2 = g_le[(size_t)idx*2 + 1];
    #pragma unroll
    for (int c = 0; c < CN; c++){
        float v = __ldg(Wf + c*3)*i0 + __ldg(Wf + c*3 + 1)*i1 + __ldg(Wf + c*3 + 2)*i2 + __ldg(bf + c);
        g_h[0][((size_t)(b*CN + c))*GP + g] = v;
    }
}

// ---------------- forward partial rfft2: modes kx in {0..7,56..63}, ky 0..7 ----------------
__global__ void k_fwd(int src){
    __shared__ float  img[4096];
    __shared__ float2 t[64][8];
    __shared__ float2 tw[64];   // e^{-2pi i k/64}
    int bc = blockIdx.x, tid = threadIdx.x;
    const float* hp = g_h[src] + (size_t)bc*GP;
    for (int i = tid; i < 4096; i += 256) img[i] = hp[i];
    if (tid < 64){ float s, c; sincospif(-(float)tid/32.0f, &s, &c); tw[tid] = make_float2(c, s); }
    __syncthreads();
    #pragma unroll
    for (int k = 0; k < 2; k++){
        int task = k*256 + tid;
        int x = task >> 3, ky = task & 7;
        float re = 0, im = 0;
        for (int y = 0; y < 64; y++){
            float v = img[(x << 6) + y];
            float2 w = tw[(ky*y) & 63];
            re += v*w.x; im += v*w.y;
        }
        t[x][ky] = make_float2(re, im);
    }
    __syncthreads();
    if (tid < 128){
        int kxi = tid >> 3, ky = tid & 7;
        int kx = (kxi < 8) ? kxi : 48 + kxi;
        float re = 0, im = 0;
        for (int x = 0; x < 64; x++){
            float2 tv = t[x][ky];
            float2 w = tw[(kx*x) & 63];
            re += tv.x*w.x - tv.y*w.y;
            im += tv.x*w.y + tv.y*w.x;
        }
        g_xf[(size_t)bc*128 + tid] = make_float2(re, im);
    }
}

// ---------------- mode mixing: of[o,m] = sum_i xf[i,m] * w[i,o,m] ----------------
__global__ void k_mix(const float* __restrict__ w1, const float* __restrict__ w2, int layer){
    __shared__ float2 sxf[8][32];
    int blk = blockIdx.x, tid = threadIdx.x;
    int b = blk >> 4, mg = blk & 15;
    {
        int mm = tid >> 5, ch = tid & 31;
        int m = mg*8 + mm;
        sxf[mm][ch] = g_xf[(size_t)(b*CN + ch)*128 + m];
    }
    __syncthreads();
    int o = tid & 31, mm = tid >> 5;
    int m = mg*8 + mm;
    int kxi = m >> 3, ky = m & 7;
    const float* wb;
    int mx;
    if (kxi < 8){ wb = w1; mx = kxi; } else { wb = w2; mx = kxi - 8; }
    wb += (size_t)layer*65536 + (size_t)o*128 + mx*16 + ky*2;
    float re = 0, im = 0;
    #pragma unroll 8
    for (int i = 0; i < 32; i++){
        float wr = __ldg(wb + (size_t)i*4096);
        float wi = __ldg(wb + (size_t)i*4096 + 1);
        float2 xv = sxf[mm][i];
        re += xv.x*wr - xv.y*wi;
        im += xv.x*wi + xv.y*wr;
    }
    g_of[(size_t)(b*CN + o)*128 + m] = make_float2(re, im);
}

// ---------------- inverse truncated rfft2 + pointwise conv + gelu ----------------
__global__ void k_inv(int src, const float* __restrict__ wpt, const float* __restrict__ wptb,
                      int layer, int dogelu){
    __shared__ float  sin_[32][64];
    __shared__ float  sw[32][32];
    __shared__ float2 sG[32][8];
    __shared__ float2 tw[64];   // e^{+2pi i k/64}
    int blk = blockIdx.x, tid = threadIdx.x;
    int b = blk >> 6, x = blk & 63;
    for (int i = tid; i < 2048; i += 256){
        int c = i >> 6, y = i & 63;
        sin_[c][y] = g_h[src][(size_t)(b*CN + c)*GP + (x << 6) + y];
    }
    for (int i = tid; i < 1024; i += 256) sw[i >> 5][i & 31] = __ldg(wpt + layer*1024 + i);
    if (tid < 64){ float s, c; sincospif((float)tid/32.0f, &s, &c); tw[tid] = make_float2(c, s); }
    __syncthreads();
    {
        int o = tid >> 3, ky = tid & 7;
        const float2* ofp = g_of + (size_t)(b*CN + o)*128 + ky;
        float re = 0, im = 0;
        #pragma unroll
        for (int kxi = 0; kxi < 16; kxi++){
            float2 v = __ldg(ofp + kxi*8);
            int kx = (kxi < 8) ? kxi : 48 + kxi;
            float2 w = tw[(kx*x) & 63];
            re += v.x*w.x - v.y*w.y;
            im += v.x*w.y + v.y*w.x;
        }
        sG[o][ky] = make_float2(re, im);
    }
    __syncthreads();
    #pragma unroll
    for (int k = 0; k < 8; k++){
        int it = k*256 + tid;
        int o = it >> 6, y = it & 63;
        float s = 0;
        #pragma unroll 8
        for (int c = 0; c < 32; c++) s += sw[o][c]*sin_[c][y];
        float spec = 0;
        #pragma unroll
        for (int ky = 0; ky < 8; ky++){
            float2 Gv = sG[o][ky];
            float2 w = tw[(ky*y) & 63];
            float r = Gv.x*w.x - Gv.y*w.y;
            spec += (ky == 0) ? r : 2.0f*r;
        }
        float val = s + __ldg(wptb + layer*32 + o) + spec*(1.0f/4096.0f);
        if (dogelu) val = gelu(val);
        g_h[src^1][(size_t)(b*CN + o)*GP + (x << 6) + y] = val;
    }
}

// ---------------- centered partial FFT (base 65, ortho) for NU branch ----------------
__global__ void k_nufwd(int src){
    __shared__ float  img[4096];
    __shared__ float2 t[64][9];
    __shared__ float2 tw[65];   // e^{-2pi i k/65}
    int bc = blockIdx.x, tid = threadIdx.x;
    const float* hp = g_h[src] + (size_t)bc*GP;
    for (int i = tid; i < 4096; i += 256) img[i] = hp[i];
    if (tid < 65){ float s, c; sincospif(-2.0f*(float)tid/65.0f, &s, &c); tw[tid] = make_float2(c, s); }
    __syncthreads();
    for (int task = tid; task < 576; task += 256){
        int x = task/9, bb = task%9;
        int pb = bb + 57; if (pb >= 65) pb -= 65;   // (bb-8) mod 65
        float re = 0, im = 0;
        for (int y = 0; y < 64; y++){
            float v = img[(x << 6) + y];
            float2 w = tw[(pb*y) % 65];
            re += v*w.x; im += v*w.y;
        }
        t[x][bb] = make_float2(re, im);
    }
    __syncthreads();
    for (int task = tid; task < 153; task += 256){
        int ai = task/9, bb = task%9;
        int pa = ai + 57; if (pa >= 65) pa -= 65;   // (ai-8) mod 65
        float re = 0, im = 0;
        for (int x = 0; x < 64; x++){
            float2 tv = t[x][bb];
            float2 w = tw[(pa*x) % 65];
            re += tv.x*w.x - tv.y*w.y;
            im += tv.x*w.y + tv.y*w.x;
        }
        g_Fm[(size_t)bc*153 + task] = make_float2(re*(1.0f/65.0f), im*(1.0f/65.0f));
    }
}

// ---------------- images assembly (hermitian-symmetric 17x17 per (b,s)) ----------------
__global__ void k_images(const float* __restrict__ nu1, const float* __restrict__ nu2){
    __shared__ float2 sF[32*153];
    __shared__ float2 sim1[17][8];
    __shared__ float2 sim2[9];
    int blk = blockIdx.x, tid = threadIdx.x;
    int b = blk >> 4, s = blk & 15;
    for (int i = tid; i < 32*153; i += 256) sF[i] = g_Fm[(size_t)b*CN*153 + i];
    __syncthreads();
    for (int t = tid; t < 145; t += 256){
        if (t < 136){
            int ai = t >> 3, bi = t & 7;
            const float* w = nu1 + (size_t)s*272 + ai*16 + bi*2;
            float re = 0, im = 0;
            for (int c = 0; c < 32; c++){
                float2 f = sF[c*153 + ai*9 + bi];
                float wr = __ldg(w + (size_t)c*4352), wi = __ldg(w + (size_t)c*4352 + 1);
                re += f.x*wr - f.y*wi;
                im += f.x*wi + f.y*wr;
            }
            sim1[ai][bi] = make_float2(re, im);
        } else {
            int ai = t - 136;
            const float* w = nu2 + (size_t)s*18 + ai*2;
            float re = 0, im = 0;
            for (int c = 0; c < 32; c++){
                float2 f = sF[c*153 + ai*9 + 8];
                float wr = __ldg(w + (size_t)c*288), wi = __ldg(w + (size_t)c*288 + 1);
                re += f.x*wr - f.y*wi;
                im += f.x*wi + f.y*wr;
            }
            sim2[ai] = make_float2(re, im);
        }
    }
    __syncthreads();
    for (int t = tid; t < 289; t += 256){
        int x = t/17, y = t%17;
        float2 v;
        if (y < 8)       v = sim1[x][y];
        else if (y > 8){ float2 u = sim1[16-x][16-y]; v = make_float2(u.x, -u.y); }
        else {
            if (x < 8)        v = sim2[x];
            else if (x == 8)  v = make_float2(sim2[8].x, 0.0f);
            else            { float2 u = sim2[16-x]; v = make_float2(u.x, -u.y); }
        }
        g_img[(size_t)(b*SN + s)*289 + t] = v;
    }
}

// ---------------- per-(b,s) bounding box of loc ----------------
__global__ void k_minmax(const float* __restrict__ loc, const int* __restrict__ ind,
                         const int* __restrict__ sep){
    __shared__ float s0[128], s1[128], s2[128], s3[128];
    int blk = blockIdx.x, tid = threadIdx.x;
    int b = blk >> 4, s = blk & 15;
    int j0 = __ldg(sep + b*17 + s), j1 = __ldg(sep + b*17 + s + 1);
    float mn0 = 1e30f, mn1 = 1e30f, mx0 = -1e30f, mx1 = -1e30f;
    for (int j = j0 + tid; j < j1; j += blockDim.x){
        int p = __ldg(ind + (size_t)b*NYP + j);
        float l0 = __ldg(loc + ((size_t)b*NYP + p)*2);
        float l1 = __ldg(loc + ((size_t)b*NYP + p)*2 + 1);
        mn0 = fminf(mn0, l0); mx0 = fmaxf(mx0, l0);
        mn1 = fminf(mn1, l1); mx1 = fmaxf(mx1, l1);
    }
    s0[tid] = mn0; s1[tid] = mn1; s2[tid] = mx0; s3[tid] = mx1;
    __syncthreads();
    for (int st = 64; st; st >>= 1){
        if (tid < st){
            s0[tid] = fminf(s0[tid], s0[tid+st]);
            s1[tid] = fminf(s1[tid], s1[tid+st]);
            s2[tid] = fmaxf(s2[tid], s2[tid+st]);
            s3[tid] = fmaxf(s3[tid], s3[tid+st]);
        }
        __syncthreads();
    }
    if (tid == 0){
        g_mn[(b*SN + s)*2 + 0] = s0[0];
        g_mn[(b*SN + s)*2 + 1] = s1[0];
        g_mx[(b*SN + s)*2 + 0] = s2[0];
        g_mx[(b*SN + s)*2 + 1] = s3[0];
    }
}

// ---------------- exact type-2 NUDFT per point ----------------
__global__ void k_nudft(const float* __restrict__ loc, const int* __restrict__ ind,
                        const int* __restrict__ sep, const float* __restrict__ nuw,
                        const float* __restrict__ nub){
    __shared__ float2 simg[289];
    int blk = blockIdx.x, tid = threadIdx.x;
    int b = blk >> 4, s = blk & 15;
    for (int i = tid; i < 289; i += 256) simg[i] = g_img[(size_t)(b*SN + s)*289 + i];
    __syncthreads();
    int j0 = __ldg(sep + b*17 + s), j1 = __ldg(sep + b*17 + s + 1);
    float mn0 = g_mn[(b*SN+s)*2], mn1 = g_mn[(b*SN+s)*2+1];
    float mx0 = g_mx[(b*SN+s)*2], mx1 = g_mx[(b*SN+s)*2+1];
    float wS = __ldg(nuw + s), bS = __ldg(nub + s);
    for (int j = j0 + tid; j < j1; j += 256){
        int p = __ldg(ind + (size_t)b*NYP + j);
        float l0 = __ldg(loc + ((size_t)b*NYP + p)*2);
        float l1 = __ldg(loc + ((size_t)b*NYP + p)*2 + 1);
        float om0 = (l0 - mn0)/(mx0 - mn0 + 1e-6f)*6.283185307179586f - 3.141592653589793f;
        float om1 = (l1 - mn1)/(mx1 - mn1 + 1e-6f)*6.283185307179586f - 3.141592653589793f;
        float sx, cx; sincosf(om0, &sx, &cx); float2 e0 = make_float2(cx, sx);
        float sy, cy; sincosf(om1, &sy, &cy); float2 e1 = make_float2(cy, sy);
        float2 ex[17], ey[17];
        ex[8] = make_float2(1.f, 0.f); ey[8] = make_float2(1.f, 0.f);
        #pragma unroll
        for (int k = 9; k < 17; k++){ ex[k] = cmul(ex[k-1], e0); ey[k] = cmul(ey[k-1], e1); }
        #pragma unroll
        for (int k = 0; k < 8; k++){
            ex[k] = make_float2(ex[16-k].x, -ex[16-k].y);
            ey[k] = make_float2(ey[16-k].x, -ey[16-k].y);
        }
        float acc = 0;
        #pragma unroll
        for (int x = 0; x < 17; x++){
            float rr = 0, ri = 0;
            #pragma unroll
            for (int y = 0; y < 17; y++){
                float2 a = simg[x*17 + y];
                float2 e = ey[y];
                rr += a.x*e.x - a.y*e.y;
                ri += a.x*e.y + a.y*e.x;
            }
            acc += rr*ex[x].x - ri*ex[x].y;
        }
        g_nu[(size_t)b*NYP + p] = acc*(1.0f/17.0f)*wS + bS;
    }
}

// ---------------- fc1 (gelu) + fc2 -> hl (B,G) ----------------
__global__ void k_fc12(int src, const float* __restrict__ W1, const float* __restrict__ b1,
                       const float* __restrict__ W2, const float* __restrict__ b2){
    __shared__ float sW1[128*32];
    __shared__ float sb1[128];
    __shared__ float sW2[128];
    int tid = threadIdx.x;
    for (int i = tid; i < 4096; i += 256) sW1[i] = __ldg(W1 + i);
    if (tid < 128){ sb1[tid] = __ldg(b1 + tid); sW2[tid] = __ldg(W2 + tid); }
    __syncthreads();
    int idx = blockIdx.x*256 + tid;
    if (idx >= BN*GP) return;
    int b = idx >> 12, g = idx & (GP-1);
    float hv[32];
    #pragma unroll
    for (int c = 0; c < 32; c++) hv[c] = g_h[src][(size_t)(b*CN + c)*GP + g];
    float acc = 0;
    #pragma unroll 4
    for (int j = 0; j < 128; j++){
        float a = sb1[j];
        #pragma unroll
        for (int c = 0; c < 32; c++) a += sW1[j*32 + c]*hv[c];
        a = gelu(a);
        acc += a*sW2[j];
    }
    g_hl[idx] = acc + __ldg(b2);
}

// ---------------- W_de3 matvec + add NU branch -> output ----------------
__global__ void k_de3(const float* __restrict__ W, const float* __restrict__ bias,
                      float* __restrict__ out){
    int warp = (blockIdx.x*blockDim.x + threadIdx.x) >> 5;
    int lane = threadIdx.x & 31;
    if (warp >= NYP) return;
    const float4* Wr = reinterpret_cast<const float4*>(W + (size_t)warp*GP);
    float acc[4] = {0,0,0,0};
    for (int i = lane; i < GP/4; i += 32){
        float4 w = __ldg(Wr + i);
        #pragma unroll
        for (int b = 0; b < 4; b++){
            float4 h = *reinterpret_cast<const float4*>(g_hl + (size_t)b*GP + 4*i);
            acc[b] += w.x*h.x + w.y*h.y + w.z*h.z + w.w*h.w;
        }
    }
    #pragma unroll
    for (int b = 0; b < 4; b++) acc[b] = wred(acc[b]);
    if (lane == 0){
        float bv = __ldg(bias + warp);
        #pragma unroll
        for (int b = 0; b < 4; b++)
            out[(size_t)b*NYP + warp] = acc[b] + bv + g_nu[(size_t)b*NYP + warp];
    }
}

// ---------------- host launcher ----------------
extern "C" void kernel_launch(void* const* d_in, const int* in_sizes, int n_in,
                              void* d_out, int out_size){
    const float* x    = (const float*)d_in[0];
    const float* loc  = (const float*)d_in[1];
    const int*   ind  = (const int*)  d_in[2];
    const int*   sep  = (const int*)  d_in[3];
    const float* We1  = (const float*)d_in[4];
    const float* be1  = (const float*)d_in[5];
    const float* We2  = (const float*)d_in[6];
    const float* be2  = (const float*)d_in[7];
    const float* Wfc0 = (const float*)d_in[8];
    const float* bfc0 = (const float*)d_in[9];
    const float* cw1  = (const float*)d_in[10];
    const float* cw2  = (const float*)d_in[11];
    const float* wpt  = (const float*)d_in[12];
    const float* wptb = (const float*)d_in[13];
    const float* nw1  = (const float*)d_in[14];
    const float* nw2  = (const float*)d_in[15];
    const float* nw   = (const float*)d_in[16];
    const float* nb   = (const float*)d_in[17];
    const float* Wde3 = (const float*)d_in[18];
    const float* bde3 = (const float*)d_in[19];
    const float* Wfc1 = (const float*)d_in[20];
    const float* bfc1 = (const float*)d_in[21];
    const float* Wfc2 = (const float*)d_in[22];
    const float* bfc2 = (const float*)d_in[23];
    float* out = (float*)d_out;

    k_embed1<<<512, 256>>>(We1, x, be1);
    k_embed2<<<512, 256>>>(We2, loc, be2);
    k_fc0<<<64, 256>>>(Wfc0, bfc0);

    int src = 0;
    for (int l = 0; l < 4; l++){
        k_fwd<<<128, 256>>>(src);
        k_mix<<<64, 256>>>(cw1, cw2, l);
        k_inv<<<256, 256>>>(src, wpt, wptb, l, (l < 3) ? 1 : 0);
        src ^= 1;
    }
    // src == 0 here (final h in g_h[0])

    k_nufwd<<<128, 256>>>(src);
    k_images<<<64, 256>>>(nw1, nw2);
    k_minmax<<<64, 128>>>(loc, ind, sep);
    k_nudft<<<64, 256>>>(loc, ind, sep, nw, nb);

    k_fc12<<<64, 256>>>(src, Wfc1, bfc1, Wfc2, bfc2);
    k_de3<<<1024, 256>>>(Wde3, bde3, out);
}

// round 2
// speedup vs baseline: 1.1992x; 1.1992x over previous
#include <cuda_runtime.h>
#include <math.h>

#define BN 4
#define NX 4096
#define NYP 8192
#define GP 4096
#define CN 32
#define SN 16

// ---------------- scratch (static device globals; no allocation) ----------------
__device__ __align__(16) float  g_xe[BN*GP];
__device__ __align__(16) float  g_le[BN*GP*2];
__device__ __align__(16) float  g_h[2][BN*CN*GP];
__device__ __align__(16) float2 g_xf[BN*CN*16*8];
__device__ __align__(16) float2 g_of[BN*CN*16*8];
__device__ __align__(16) float2 g_Fm[BN*CN*17*9];
__device__ __align__(16) float2 g_img[BN*SN*17*17];
__device__ __align__(16) float  g_mn[BN*SN*2];
__device__ __align__(16) float  g_mx[BN*SN*2];
__device__ __align__(16) float  g_hl[BN*GP];
__device__ __align__(16) float  g_nu[BN*NYP];

__device__ __forceinline__ float wred(float v){
    #pragma unroll
    for (int o = 16; o; o >>= 1) v += __shfl_down_sync(0xffffffffu, v, o);
    return v;
}
__device__ __forceinline__ float2 cmul(float2 a, float2 b){
    return make_float2(a.x*b.x - a.y*b.y, a.x*b.y + a.y*b.x);
}
__device__ __forceinline__ float gelu(float v){
    return 0.5f*v*(1.0f + erff(v*0.70710678118654752f));
}

// ---------------- xe = W_embed1 @ x  (per-batch matvec) ----------------
__global__ void k_embed1(const float* __restrict__ W, const float* __restrict__ x,
                         const float* __restrict__ bias){
    int warp = (blockIdx.x*blockDim.x + threadIdx.x) >> 5;
    int lane = threadIdx.x & 31;
    if (warp >= GP) return;
    const float4* Wr = reinterpret_cast<const float4*>(W + (size_t)warp*NX);
    float acc[4] = {0,0,0,0};
    #pragma unroll 4
    for (int i = lane; i < NX/4; i += 32){
        float4 w = __ldg(Wr + i);
        #pragma unroll
        for (int b = 0; b < 4; b++){
            float4 xv = __ldg(reinterpret_cast<const float4*>(x + (size_t)b*NX) + i);
            acc[b] += w.x*xv.x + w.y*xv.y + w.z*xv.z + w.w*xv.w;
        }
    }
    #pragma unroll
    for (int b = 0; b < 4; b++) acc[b] = wred(acc[b]);
    if (lane == 0){
        float bv = bias[warp];
        #pragma unroll
        for (int b = 0; b < 4; b++) g_xe[(size_t)b*GP + warp] = acc[b] + bv;
    }
}

// ---------------- le = W_embed2 @ loc ----------------
__global__ void k_embed2(const float* __restrict__ W, const float* __restrict__ loc,
                         const float* __restrict__ bias){
    int warp = (blockIdx.x*blockDim.x + threadIdx.x) >> 5;
    int lane = threadIdx.x & 31;
    if (warp >= GP) return;
    const float4* Wr = reinterpret_cast<const float4*>(W + (size_t)warp*NYP);
    float a0[4] = {0,0,0,0}, a1[4] = {0,0,0,0};
    #pragma unroll 2
    for (int i = lane; i < NYP/4; i += 32){
        float4 w = __ldg(Wr + i);
        #pragma unroll
        for (int b = 0; b < 4; b++){
            const float4* lp = reinterpret_cast<const float4*>(loc + (size_t)b*NYP*2);
            float4 p01 = __ldg(lp + 2*i);
            float4 p23 = __ldg(lp + 2*i + 1);
            a0[b] += w.x*p01.x + w.y*p01.z + w.z*p23.x + w.w*p23.z;
            a1[b] += w.x*p01.y + w.y*p01.w + w.z*p23.y + w.w*p23.w;
        }
    }
    #pragma unroll
    for (int b = 0; b < 4; b++){ a0[b] = wred(a0[b]); a1[b] = wred(a1[b]); }
    if (lane == 0){
        float bv = bias[warp];
        #pragma unroll
        for (int b = 0; b < 4; b++){
            g_le[((size_t)b*GP + warp)*2 + 0] = a0[b] + bv;
            g_le[((size_t)b*GP + warp)*2 + 1] = a1[b] + bv;
        }
    }
}

// ---------------- fc0: (xe,le0,le1) -> 32 channels ----------------
__global__ void k_fc0(const float* __restrict__ Wf, const float* __restrict__ bf){
    int idx = blockIdx.x*blockDim.x + threadIdx.x;
    if (idx >= BN*GP) return;
    int b = idx >> 12, g = idx & (GP-1);
    float i0 = g_xe[idx];
    float i1 = g_le[(size_t)idx*2];
    float i2 = g_le[(size_t)idx*2 + 1];
    #pragma unroll
    for (int c = 0; c < CN; c++){
        float v = __ldg(Wf + c*3)*i0 + __ldg(Wf + c*3 + 1)*i1 + __ldg(Wf + c*3 + 2)*i2 + __ldg(bf + c);
        g_h[0][((size_t)(b*CN + c))*GP + g] = v;
    }
}

// ---------------- forward partial rfft2: modes kx in {0..7,56..63}, ky 0..7 ----------------
__global__ void k_fwd(int src){
    __shared__ float  img[4096];
    __shared__ float2 t[64][9];   // [x][ky] (pad col)
    __shared__ float2 tw[64];     // e^{-2pi i k/64}
    int bc = blockIdx.x, tid = threadIdx.x;
    const float4* hp = reinterpret_cast<const float4*>(g_h[src] + (size_t)bc*GP);
    float4* img4 = reinterpret_cast<float4*>(img);
    for (int i = tid; i < 1024; i += 512) img4[i] = hp[i];
    if (tid < 64){ float s, c; sincospif(-(float)tid/32.0f, &s, &c); tw[tid] = make_float2(c, s); }
    __syncthreads();
    // phase 1: y transform. 512 tasks = 64 x * 8 ky, one per thread
    {
        int x = tid >> 3, ky = tid & 7;
        const float4* row = reinterpret_cast<const float4*>(img + (x << 6));
        float re = 0, im = 0;
        #pragma unroll
        for (int i = 0; i < 16; i++){
            float4 v = row[i];
            int base = (ky*(i*4)) & 63;
            float2 w0 = tw[base];
            float2 w1 = tw[(base + ky) & 63];
            float2 w2 = tw[(base + 2*ky) & 63];
            float2 w3 = tw[(base + 3*ky) & 63];
            re += v.x*w0.x + v.y*w1.x + v.z*w2.x + v.w*w3.x;
            im += v.x*w0.y + v.y*w1.y + v.z*w2.y + v.w*w3.y;
        }
        t[x][ky] = make_float2(re, im);
    }
    __syncthreads();
    // phase 2: x transform. 128 outputs * 4 threads each
    {
        int task = tid >> 2, sub = tid & 3;
        int kxi = task >> 3, ky = task & 7;
        int kx = (kxi < 8) ? kxi : 48 + kxi;
        float re = 0, im = 0;
        #pragma unroll
        for (int i = 0; i < 16; i++){
            int x = sub + (i << 2);
            float2 tv = t[x][ky];
            float2 w = tw[(kx*x) & 63];
            re += tv.x*w.x - tv.y*w.y;
            im += tv.x*w.y + tv.y*w.x;
        }
        re += __shfl_down_sync(0xffffffffu, re, 2);
        im += __shfl_down_sync(0xffffffffu, im, 2);
        re += __shfl_down_sync(0xffffffffu, re, 1);
        im += __shfl_down_sync(0xffffffffu, im, 1);
        if (sub == 0) g_xf[(size_t)bc*128 + task] = make_float2(re, im);
    }
}

// ---------------- mode mixing: of[o,m] = sum_i xf[i,m] * w[i,o,m] ----------------
__global__ void k_mix(const float* __restrict__ w1, const float* __restrict__ w2, int layer){
    __shared__ float2 sxf[8][33];
    int blk = blockIdx.x, tid = threadIdx.x;
    int b = blk >> 4, mg = blk & 15;
    {
        int mm = tid >> 5, ch = tid & 31;
        sxf[mm][ch] = g_xf[(size_t)(b*CN + ch)*128 + mg*8 + mm];
    }
    __syncthreads();
    int o = tid >> 3, mm = tid & 7;
    int m = mg*8 + mm;
    const float* wb = (mg < 8) ? w1 : w2;
    int mx = (mg < 8) ? mg : mg - 8;
    const float2* wb2 = reinterpret_cast<const float2*>(
        wb + (size_t)layer*65536 + (size_t)o*128 + mx*16 + mm*2);
    float re = 0, im = 0;
    #pragma unroll 8
    for (int i = 0; i < 32; i++){
        float2 w = __ldg(wb2 + (size_t)i*2048);
        float2 xv = sxf[mm][i];
        re += xv.x*w.x - xv.y*w.y;
        im += xv.x*w.y + xv.y*w.x;
    }
    g_of[(size_t)(b*CN + o)*128 + m] = make_float2(re, im);
}

// ---------------- inverse truncated rfft2 + pointwise conv + gelu ----------------
__global__ void k_inv(int src, const float* __restrict__ wpt, const float* __restrict__ wptb,
                      int layer, int dogelu){
    __shared__ float  sin_[32][64];
    __shared__ float  sw[32][32];
    __shared__ float2 sG[32][8];
    __shared__ float2 tw[64];   // e^{+2pi i k/64}
    int blk = blockIdx.x, tid = threadIdx.x;
    int b = blk >> 6, x = blk & 63;
    const float* hb = g_h[src] + (size_t)b*CN*GP + (x << 6);
    for (int i = tid; i < 512; i += 256){
        int c = i >> 4, q = i & 15;
        reinterpret_cast<float4*>(sin_[c])[q] =
            __ldg(reinterpret_cast<const float4*>(hb + (size_t)c*GP) + q);
    }
    for (int i = tid; i < 1024; i += 256) sw[i >> 5][i & 31] = __ldg(wpt + layer*1024 + i);
    if (tid < 64){ float s, c; sincospif((float)tid/32.0f, &s, &c); tw[tid] = make_float2(c, s); }
    __syncthreads();
    // spectral x-phase: G[o][ky] = sum_kx of[o,kx,ky] e^{+2pi i kx x/64}
    {
        int o = tid >> 3, ky = tid & 7;
        const float2* ofp = g_of + (size_t)(b*CN + o)*128 + ky;
        float re = 0, im = 0;
        #pragma unroll
        for (int kxi = 0; kxi < 16; kxi++){
            float2 v = __ldg(ofp + kxi*8);
            int kx = (kxi < 8) ? kxi : 48 + kxi;
            float2 w = tw[(kx*x) & 63];
            re += v.x*w.x - v.y*w.y;
            im += v.x*w.y + v.y*w.x;
        }
        sG[o][ky] = make_float2(re, im);
    }
    __syncthreads();
    float* outp = g_h[src^1] + (size_t)b*CN*GP + (x << 6);
    // 512 tasks = 32 o * 16 y-quads
    #pragma unroll
    for (int k = 0; k < 2; k++){
        int task = k*256 + tid;
        int o = task >> 4, y4 = task & 15;
        float4 acc = make_float4(0.f, 0.f, 0.f, 0.f);
        #pragma unroll 8
        for (int c = 0; c < 32; c++){
            float wv = sw[o][c];
            float4 v = reinterpret_cast<const float4*>(sin_[c])[y4];
            acc.x += wv*v.x; acc.y += wv*v.y; acc.z += wv*v.z; acc.w += wv*v.w;
        }
        float spec[4] = {0,0,0,0};
        #pragma unroll
        for (int ky = 0; ky < 8; ky++){
            float2 G = sG[o][ky];
            float scl = ky ? 2.0f : 1.0f;
            #pragma unroll
            for (int j = 0; j < 4; j++){
                int y = y4*4 + j;
                float2 w = tw[(ky*y) & 63];
                spec[j] += scl*(G.x*w.x - G.y*w.y);
            }
        }
        float bb = __ldg(wptb + layer*32 + o);
        float4 r;
        r.x = acc.x + bb + spec[0]*(1.0f/4096.0f);
        r.y = acc.y + bb + spec[1]*(1.0f/4096.0f);
        r.z = acc.z + bb + spec[2]*(1.0f/4096.0f);
        r.w = acc.w + bb + spec[3]*(1.0f/4096.0f);
        if (dogelu){ r.x = gelu(r.x); r.y = gelu(r.y); r.z = gelu(r.z); r.w = gelu(r.w); }
        reinterpret_cast<float4*>(outp + (size_t)o*GP)[y4] = r;
    }
}

// ---------------- centered partial FFT (base 65, ortho) for NU branch ----------------
__global__ void k_nufwd(int src){
    __shared__ float  img[4096];
    __shared__ float2 t[64][9];   // [x][bb]
    __shared__ float2 tw[65];     // e^{-2pi i k/65}
    int bc = blockIdx.x, tid = threadIdx.x;
    const float4* hp = reinterpret_cast<const float4*>(g_h[src] + (size_t)bc*GP);
    float4* img4 = reinterpret_cast<float4*>(img);
    for (int i = tid; i < 1024; i += 576) img4[i] = hp[i];
    if (tid < 65){ float s, c; sincospif(-2.0f*(float)tid/65.0f, &s, &c); tw[tid] = make_float2(c, s); }
    __syncthreads();
    // phase 1: 576 tasks = 64 x * 9 b-modes, one per thread
    {
        int x = tid/9, bb = tid - x*9;
        int pb = bb + 57; if (pb >= 65) pb -= 65;   // (bb-8) mod 65
        const float4* row = reinterpret_cast<const float4*>(img + (x << 6));
        float re = 0, im = 0;
        int idx = 0;
        #pragma unroll
        for (int i = 0; i < 16; i++){
            float4 v = row[i];
            float2 w0 = tw[idx]; idx += pb; if (idx >= 65) idx -= 65;
            float2 w1 = tw[idx]; idx += pb; if (idx >= 65) idx -= 65;
            float2 w2 = tw[idx]; idx += pb; if (idx >= 65) idx -= 65;
            float2 w3 = tw[idx]; idx += pb; if (idx >= 65) idx -= 65;
            re += v.x*w0.x + v.y*w1.x + v.z*w2.x + v.w*w3.x;
            im += v.x*w0.y + v.y*w1.y + v.z*w2.y + v.w*w3.y;
        }
        t[x][bb] = make_float2(re, im);
    }
    __syncthreads();
    // phase 2: 153 tasks = 17 a-modes * 9 b-modes, 2 threads each
    if (tid < 306){
        int task = tid >> 1, sub = tid & 1;
        int ai = task/9, bb = task - ai*9;
        int pa = ai + 57; if (pa >= 65) pa -= 65;   // (ai-8) mod 65
        float re = 0, im = 0;
        int idx = (pa*sub) % 65;
        int step = (pa*2) % 65;
        #pragma unroll
        for (int i = 0; i < 32; i++){
            int x = sub + (i << 1);
            float2 tv = t[x][bb];
            float2 w = tw[idx]; idx += step; if (idx >= 65) idx -= 65;
            re += tv.x*w.x - tv.y*w.y;
            im += tv.x*w.y + tv.y*w.x;
        }
        re += __shfl_down_sync(0xffffffffu, re, 1);
        im += __shfl_down_sync(0xffffffffu, im, 1);
        if (sub == 0) g_Fm[(size_t)bc*153 + task] = make_float2(re*(1.0f/65.0f), im*(1.0f/65.0f));
    }
}

// ---------------- images assembly (hermitian-symmetric 17x17 per (b,s)) ----------------
__global__ void k_images(const float* __restrict__ nu1, const float* __restrict__ nu2){
    __shared__ float2 sF[32*153];
    __shared__ float2 sim1[17][8];
    __shared__ float2 sim2[9];
    int blk = blockIdx.x, tid = threadIdx.x;
    int b = blk >> 4, s = blk & 15;
    for (int i = tid; i < 32*153; i += 256) sF[i] = g_Fm[(size_t)b*CN*153 + i];
    __syncthreads();
    for (int t = tid; t < 145; t += 256){
        if (t < 136){
            int ai = t >> 3, bi = t & 7;
            const float2* w = reinterpret_cast<const float2*>(nu1 + (size_t)s*272 + ai*16 + bi*2);
            float re = 0, im = 0;
            for (int c = 0; c < 32; c++){
                float2 f = sF[c*153 + ai*9 + bi];
                float2 wv = __ldg(w + (size_t)c*2176);
                re += f.x*wv.x - f.y*wv.y;
                im += f.x*wv.y + f.y*wv.x;
            }
            sim1[ai][bi] = make_float2(re, im);
        } else {
            int ai = t - 136;
            const float2* w = reinterpret_cast<const float2*>(nu2 + (size_t)s*18 + ai*2);
            float re = 0, im = 0;
            for (int c = 0; c < 32; c++){
                float2 f = sF[c*153 + ai*9 + 8];
                float2 wv = __ldg(w + (size_t)c*144);
                re += f.x*wv.x - f.y*wv.y;
                im += f.x*wv.y + f.y*wv.x;
            }
            sim2[ai] = make_float2(re, im);
        }
    }
    __syncthreads();
    for (int t = tid; t < 289; t += 256){
        int x = t/17, y = t%17;
        float2 v;
        if (y < 8)       v = sim1[x][y];
        else if (y > 8){ float2 u = sim1[16-x][16-y]; v = make_float2(u.x, -u.y); }
        else {
            if (x < 8)        v = sim2[x];
            else if (x == 8)  v = make_float2(sim2[8].x, 0.0f);
            else            { float2 u = sim2[16-x]; v = make_float2(u.x, -u.y); }
        }
        g_img[(size_t)(b*SN + s)*289 + t] = v;
    }
}

// ---------------- per-(b,s) bounding box of loc ----------------
__global__ void k_minmax(const float* __restrict__ loc, const int* __restrict__ ind,
                         const int* __restrict__ sep){
    __shared__ float s0[128], s1[128], s2[128], s3[128];
    int blk = blockIdx.x, tid = threadIdx.x;
    int b = blk >> 4, s = blk & 15;
    int j0 = __ldg(sep + b*17 + s), j1 = __ldg(sep + b*17 + s + 1);
    float mn0 = 1e30f, mn1 = 1e30f, mx0 = -1e30f, mx1 = -1e30f;
    for (int j = j0 + tid; j < j1; j += blockDim.x){
        int p = __ldg(ind + (size_t)b*NYP + j);
        float l0 = __ldg(loc + ((size_t)b*NYP + p)*2);
        float l1 = __ldg(loc + ((size_t)b*NYP + p)*2 + 1);
        mn0 = fminf(mn0, l0); mx0 = fmaxf(mx0, l0);
        mn1 = fminf(mn1, l1); mx1 = fmaxf(mx1, l1);
    }
    s0[tid] = mn0; s1[tid] = mn1; s2[tid] = mx0; s3[tid] = mx1;
    __syncthreads();
    for (int st = 64; st; st >>= 1){
        if (tid < st){
            s0[tid] = fminf(s0[tid], s0[tid+st]);
            s1[tid] = fminf(s1[tid], s1[tid+st]);
            s2[tid] = fmaxf(s2[tid], s2[tid+st]);
            s3[tid] = fmaxf(s3[tid], s3[tid+st]);
        }
        __syncthreads();
    }
    if (tid == 0){
        g_mn[(b*SN + s)*2 + 0] = s0[0];
        g_mn[(b*SN + s)*2 + 1] = s1[0];
        g_mx[(b*SN + s)*2 + 0] = s2[0];
        g_mx[(b*SN + s)*2 + 1] = s3[0];
    }
}

// ---------------- exact type-2 NUDFT per point (grid split 4-way per (b,s)) ----------------
__global__ void k_nudft(const float* __restrict__ loc, const int* __restrict__ ind,
                        const int* __restrict__ sep, const float* __restrict__ nuw,
                        const float* __restrict__ nub){
    __shared__ float2 simg[289];
    int blk = blockIdx.x, tid = threadIdx.x;
    int q = blk & 3, s = (blk >> 2) & 15, b = blk >> 6;
    for (int i = tid; i < 289; i += 128) simg[i] = g_img[(size_t)(b*SN + s)*289 + i];
    __syncthreads();
    int j0 = __ldg(sep + b*17 + s), j1 = __ldg(sep + b*17 + s + 1);
    int cnt = j1 - j0;
    int per = (cnt + 3) >> 2;
    int js = j0 + q*per;
    int je = js + per; if (je > j1) je = j1;
    float mn0 = g_mn[(b*SN+s)*2], mn1 = g_mn[(b*SN+s)*2+1];
    float mx0 = g_mx[(b*SN+s)*2], mx1 = g_mx[(b*SN+s)*2+1];
    float wS = __ldg(nuw + s), bS = __ldg(nub + s);
    for (int j = js + tid; j < je; j += 128){
        int p = __ldg(ind + (size_t)b*NYP + j);
        float l0 = __ldg(loc + ((size_t)b*NYP + p)*2);
        float l1 = __ldg(loc + ((size_t)b*NYP + p)*2 + 1);
        float om0 = (l0 - mn0)/(mx0 - mn0 + 1e-6f)*6.283185307179586f - 3.141592653589793f;
        float om1 = (l1 - mn1)/(mx1 - mn1 + 1e-6f)*6.283185307179586f - 3.141592653589793f;
        float sx, cx; sincosf(om0, &sx, &cx); float2 e0 = make_float2(cx, sx);
        float sy, cy; sincosf(om1, &sy, &cy); float2 e1 = make_float2(cy, sy);
        float2 ex[17], ey[17];
        ex[8] = make_float2(1.f, 0.f); ey[8] = make_float2(1.f, 0.f);
        #pragma unroll
        for (int k = 9; k < 17; k++){ ex[k] = cmul(ex[k-1], e0); ey[k] = cmul(ey[k-1], e1); }
        #pragma unroll
        for (int k = 0; k < 8; k++){
            ex[k] = make_float2(ex[16-k].x, -ex[16-k].y);
            ey[k] = make_float2(ey[16-k].x, -ey[16-k].y);
        }
        float acc = 0;
        #pragma unroll
        for (int x = 0; x < 17; x++){
            float rr = 0, ri = 0;
            #pragma unroll
            for (int y = 0; y < 17; y++){
                float2 a = simg[x*17 + y];
                float2 e = ey[y];
                rr += a.x*e.x - a.y*e.y;
                ri += a.x*e.y + a.y*e.x;
            }
            acc += rr*ex[x].x - ri*ex[x].y;
        }
        g_nu[(size_t)b*NYP + p] = acc*(1.0f/17.0f)*wS + bS;
    }
}

// ---------------- fc1 (gelu) + fc2 -> hl (B,G) ----------------
__global__ void k_fc12(int src, const float* __restrict__ W1, const float* __restrict__ b1,
                       const float* __restrict__ W2, const float* __restrict__ b2){
    __shared__ float sW1[128*32];
    __shared__ float sb1[128];
    __shared__ float sW2[128];
    int tid = threadIdx.x;
    for (int i = tid; i < 4096; i += 256) sW1[i] = __ldg(W1 + i);
    if (tid < 128){ sb1[tid] = __ldg(b1 + tid); sW2[tid] = __ldg(W2 + tid); }
    __syncthreads();
    int idx = blockIdx.x*256 + tid;
    if (idx >= BN*GP) return;
    int b = idx >> 12, g = idx & (GP-1);
    float hv[32];
    #pragma unroll
    for (int c = 0; c < 32; c++) hv[c] = g_h[src][(size_t)(b*CN + c)*GP + g];
    float acc = 0;
    #pragma unroll 4
    for (int j = 0; j < 128; j++){
        float a = sb1[j];
        #pragma unroll
        for (int c = 0; c < 32; c++) a += sW1[j*32 + c]*hv[c];
        a = gelu(a);
        acc += a*sW2[j];
    }
    g_hl[idx] = acc + __ldg(b2);
}

// ---------------- W_de3 matvec + add NU branch -> output ----------------
__global__ void k_de3(const float* __restrict__ W, const float* __restrict__ bias,
                      float* __restrict__ out){
    int warp = (blockIdx.x*blockDim.x + threadIdx.x) >> 5;
    int lane = threadIdx.x & 31;
    if (warp >= NYP) return;
    const float4* Wr = reinterpret_cast<const float4*>(W + (size_t)warp*GP);
    float acc[4] = {0,0,0,0};
    #pragma unroll 4
    for (int i = lane; i < GP/4; i += 32){
        float4 w = __ldg(Wr + i);
        #pragma unroll
        for (int b = 0; b < 4; b++){
            float4 h = *reinterpret_cast<const float4*>(g_hl + (size_t)b*GP + 4*i);
            acc[b] += w.x*h.x + w.y*h.y + w.z*h.z + w.w*h.w;
        }
    }
    #pragma unroll
    for (int b = 0; b < 4; b++) acc[b] = wred(acc[b]);
    if (lane == 0){
        float bv = __ldg(bias + warp);
        #pragma unroll
        for (int b = 0; b < 4; b++)
            out[(size_t)b*NYP + warp] = acc[b] + bv + g_nu[(size_t)b*NYP + warp];
    }
}

// ---------------- host launcher ----------------
extern "C" void kernel_launch(void* const* d_in, const int* in_sizes, int n_in,
                              void* d_out, int out_size){
    const float* x    = (const float*)d_in[0];
    const float* loc  = (const float*)d_in[1];
    const int*   ind  = (const int*)  d_in[2];
    const int*   sep  = (const int*)  d_in[3];
    const float* We1  = (const float*)d_in[4];
    const float* be1  = (const float*)d_in[5];
    const float* We2  = (const float*)d_in[6];
    const float* be2  = (const float*)d_in[7];
    const float* Wfc0 = (const float*)d_in[8];
    const float* bfc0 = (const float*)d_in[9];
    const float* cw1  = (const float*)d_in[10];
    const float* cw2  = (const float*)d_in[11];
    const float* wpt  = (const float*)d_in[12];
    const float* wptb = (const float*)d_in[13];
    const float* nw1  = (const float*)d_in[14];
    const float* nw2  = (const float*)d_in[15];
    const float* nw   = (const float*)d_in[16];
    const float* nb   = (const float*)d_in[17];
    const float* Wde3 = (const float*)d_in[18];
    const float* bde3 = (const float*)d_in[19];
    const float* Wfc1 = (const float*)d_in[20];
    const float* bfc1 = (const float*)d_in[21];
    const float* Wfc2 = (const float*)d_in[22];
    const float* bfc2 = (const float*)d_in[23];
    float* out = (float*)d_out;

    k_minmax<<<64, 128>>>(loc, ind, sep);
    k_embed1<<<512, 256>>>(We1, x, be1);
    k_embed2<<<512, 256>>>(We2, loc, be2);
    k_fc0<<<64, 256>>>(Wfc0, bfc0);

    int src = 0;
    for (int l = 0; l < 4; l++){
        k_fwd<<<128, 512>>>(src);
        k_mix<<<64, 256>>>(cw1, cw2, l);
        k_inv<<<256, 256>>>(src, wpt, wptb, l, (l < 3) ? 1 : 0);
        src ^= 1;
    }
    // src == 0 here (final h in g_h[0])

    k_nufwd<<<128, 576>>>(src);
    k_images<<<64, 256>>>(nw1, nw2);
    k_nudft<<<256, 128>>>(loc, ind, sep, nw, nb);

    k_fc12<<<64, 256>>>(src, Wfc1, bfc1, Wfc2, bfc2);
    k_de3<<<1024, 256>>>(Wde3, bde3, out);
}

// round 4
// speedup vs baseline: 1.3785x; 1.1495x over previous
#include <cuda_runtime.h>
#include <math.h>

#define BN 4
#define NX 4096
#define NYP 8192
#define GP 4096
#define CN 32
#define SN 16
#define NB 128
#define NT 512

// ---------------- scratch (static device globals; no allocation) ----------------
__device__ __align__(16) float  g_xe[BN*GP];
__device__ __align__(16) float  g_le[BN*GP*2];
__device__ __align__(16) float  g_h[2][BN*CN*GP];
__device__ __align__(16) float2 g_xf[BN*CN*16*8];
__device__ __align__(16) float2 g_of[BN*CN*16*8];
__device__ __align__(16) float2 g_Fm[BN*CN*17*9];
__device__ __align__(16) float2 g_img[BN*SN*17*17];
__device__ __align__(16) float  g_mn[BN*SN*2];
__device__ __align__(16) float  g_mx[BN*SN*2];
__device__ __align__(16) float  g_hl[BN*GP];
__device__ __align__(16) float  g_nu[BN*NYP];

// grid barrier state
__device__ unsigned g_cnt = 0;
__device__ volatile unsigned g_gen = 0;

__device__ __forceinline__ void gridbar(){
    __syncthreads();
    if (threadIdx.x == 0){
        unsigned gen = g_gen;
        __threadfence();
        unsigned old = atomicInc(&g_cnt, NB - 1);
        if (old == NB - 1){
            __threadfence();
            g_gen = gen + 1;
        } else {
            while (g_gen == gen) { __nanosleep(20); }
        }
        __threadfence();
    }
    __syncthreads();
}

__device__ __forceinline__ float wred(float v){
    #pragma unroll
    for (int o = 16; o; o >>= 1) v += __shfl_down_sync(0xffffffffu, v, o);
    return v;
}
__device__ __forceinline__ float2 cmul(float2 a, float2 b){
    return make_float2(a.x*b.x - a.y*b.y, a.x*b.y + a.y*b.x);
}
__device__ __forceinline__ float gelu(float v){
    return 0.5f*v*(1.0f + erff(v*0.70710678118654752f));
}

union SmemU {
    struct { float img[4096]; float2 t[64][9]; float2 tw[65]; } fwd;
    struct { float sin_[2][32][64]; float sw[32][32]; float2 sG[2][32][8]; float2 tw[64]; } inv;
    struct { float2 sim1[17][8]; float2 sim2[9]; } img;
    struct { float2 simg[289]; } nud;
    struct { float sW1[128*32]; float sb1[128]; float sW2[128]; } fc12;
    struct { float m0[NT]; float m1[NT]; float m2[NT]; float m3[NT]; } mm;
};

__global__ __launch_bounds__(NT, 1) void k_mega(
    const float* __restrict__ x,    const float* __restrict__ loc,
    const int*   __restrict__ ind,  const int*   __restrict__ sep,
    const float* __restrict__ We1,  const float* __restrict__ be1,
    const float* __restrict__ We2,  const float* __restrict__ be2,
    const float* __restrict__ Wfc0, const float* __restrict__ bfc0,
    const float* __restrict__ cw1,  const float* __restrict__ cw2,
    const float* __restrict__ wpt,  const float* __restrict__ wptb,
    const float* __restrict__ nw1,  const float* __restrict__ nw2,
    const float* __restrict__ nw,   const float* __restrict__ nb,
    const float* __restrict__ Wde3, const float* __restrict__ bde3,
    const float* __restrict__ Wfc1, const float* __restrict__ bfc1,
    const float* __restrict__ Wfc2, const float* __restrict__ bfc2,
    float* __restrict__ out)
{
    __shared__ SmemU S;
    const int bk = blockIdx.x;
    const int tid = threadIdx.x;
    const int warp = tid >> 5;
    const int lane = tid & 31;
    const int gwarp = bk*16 + warp;        // 0..2047

    // ================= PHASE E: embed1 + embed2 + minmax =================
    #pragma unroll
    for (int rr = 0; rr < 2; rr++){
        int r = gwarp + rr*2048;
        const float4* Wr = reinterpret_cast<const float4*>(We1 + (size_t)r*NX);
        float acc[4] = {0,0,0,0};
        #pragma unroll 4
        for (int i = lane; i < NX/4; i += 32){
            float4 w = __ldg(Wr + i);
            #pragma unroll
            for (int b = 0; b < 4; b++){
                float4 xv = __ldg(reinterpret_cast<const float4*>(x + (size_t)b*NX) + i);
                acc[b] += w.x*xv.x + w.y*xv.y + w.z*xv.z + w.w*xv.w;
            }
        }
        #pragma unroll
        for (int b = 0; b < 4; b++) acc[b] = wred(acc[b]);
        if (lane == 0){
            float bv = __ldg(be1 + r);
            #pragma unroll
            for (int b = 0; b < 4; b++) g_xe[(size_t)b*GP + r] = acc[b] + bv;
        }
    }
    #pragma unroll
    for (int rr = 0; rr < 2; rr++){
        int r = gwarp + rr*2048;
        const float4* Wr = reinterpret_cast<const float4*>(We2 + (size_t)r*NYP);
        float a0[4] = {0,0,0,0}, a1[4] = {0,0,0,0};
        #pragma unroll 2
        for (int i = lane; i < NYP/4; i += 32){
            float4 w = __ldg(Wr + i);
            #pragma unroll
            for (int b = 0; b < 4; b++){
                const float4* lp = reinterpret_cast<const float4*>(loc + (size_t)b*NYP*2);
                float4 p01 = __ldg(lp + 2*i);
                float4 p23 = __ldg(lp + 2*i + 1);
                a0[b] += w.x*p01.x + w.y*p01.z + w.z*p23.x + w.w*p23.z;
                a1[b] += w.x*p01.y + w.y*p01.w + w.z*p23.y + w.w*p23.w;
            }
        }
        #pragma unroll
        for (int b = 0; b < 4; b++){ a0[b] = wred(a0[b]); a1[b] = wred(a1[b]); }
        if (lane == 0){
            float bv = __ldg(be2 + r);
            #pragma unroll
            for (int b = 0; b < 4; b++){
                g_le[((size_t)b*GP + r)*2 + 0] = a0[b] + bv;
                g_le[((size_t)b*GP + r)*2 + 1] = a1[b] + bv;
            }
        }
    }
    if (bk < 64){
        int b = bk >> 4, s = bk & 15;
        int j0 = __ldg(sep + b*17 + s), j1 = __ldg(sep + b*17 + s + 1);
        float mn0 = 1e30f, mn1 = 1e30f, mx0 = -1e30f, mx1 = -1e30f;
        for (int j = j0 + tid; j < j1; j += NT){
            int p = __ldg(ind + (size_t)b*NYP + j);
            float l0 = __ldg(loc + ((size_t)b*NYP + p)*2);
            float l1 = __ldg(loc + ((size_t)b*NYP + p)*2 + 1);
            mn0 = fminf(mn0, l0); mx0 = fmaxf(mx0, l0);
            mn1 = fminf(mn1, l1); mx1 = fmaxf(mx1, l1);
        }
        S.mm.m0[tid] = mn0; S.mm.m1[tid] = mn1; S.mm.m2[tid] = mx0; S.mm.m3[tid] = mx1;
        __syncthreads();
        for (int st = NT/2; st; st >>= 1){
            if (tid < st){
                S.mm.m0[tid] = fminf(S.mm.m0[tid], S.mm.m0[tid+st]);
                S.mm.m1[tid] = fminf(S.mm.m1[tid], S.mm.m1[tid+st]);
                S.mm.m2[tid] = fmaxf(S.mm.m2[tid], S.mm.m2[tid+st]);
                S.mm.m3[tid] = fmaxf(S.mm.m3[tid], S.mm.m3[tid+st]);
            }
            __syncthreads();
        }
        if (tid == 0){
            g_mn[(b*SN + s)*2 + 0] = S.mm.m0[0];
            g_mn[(b*SN + s)*2 + 1] = S.mm.m1[0];
            g_mx[(b*SN + s)*2 + 0] = S.mm.m2[0];
            g_mx[(b*SN + s)*2 + 1] = S.mm.m3[0];
        }
    }
    gridbar();

    // ================= PHASE F0: fc0 =================
    {
        int t = bk*NT + tid;
        if (t < BN*GP){
            int b = t >> 12, g = t & (GP-1);
            float i0 = g_xe[t];
            float i1 = g_le[(size_t)t*2];
            float i2 = g_le[(size_t)t*2 + 1];
            #pragma unroll
            for (int c = 0; c < CN; c++){
                float v = __ldg(Wfc0 + c*3)*i0 + __ldg(Wfc0 + c*3 + 1)*i1
                        + __ldg(Wfc0 + c*3 + 2)*i2 + __ldg(bfc0 + c);
                g_h[0][((size_t)(b*CN + c))*GP + g] = v;
            }
        }
    }
    gridbar();

    // ================= 4 spectral layers =================
    int src = 0;
    for (int l = 0; l < 4; l++){
        // ---- FWD: block = (b,c) ----
        {
            int bc = bk;
            const float4* hp = reinterpret_cast<const float4*>(g_h[src] + (size_t)bc*GP);
            float4* img4 = reinterpret_cast<float4*>(S.fwd.img);
            for (int i = tid; i < 1024; i += NT) img4[i] = hp[i];
            if (tid < 64){ float s, c; sincospif(-(float)tid/32.0f, &s, &c); S.fwd.tw[tid] = make_float2(c, s); }
            __syncthreads();
            {
                int xx = tid >> 3, ky = tid & 7;
                const float4* row = reinterpret_cast<const float4*>(S.fwd.img + (xx << 6));
                float re = 0, im = 0;
                #pragma unroll
                for (int i = 0; i < 16; i++){
                    float4 v = row[i];
                    int base = (ky*(i*4)) & 63;
                    float2 w0 = S.fwd.tw[base];
                    float2 w1 = S.fwd.tw[(base + ky) & 63];
                    float2 w2 = S.fwd.tw[(base + 2*ky) & 63];
                    float2 w3 = S.fwd.tw[(base + 3*ky) & 63];
                    re += v.x*w0.x + v.y*w1.x + v.z*w2.x + v.w*w3.x;
                    im += v.x*w0.y + v.y*w1.y + v.z*w2.y + v.w*w3.y;
                }
                S.fwd.t[xx][ky] = make_float2(re, im);
            }
            __syncthreads();
            {
                int task = tid >> 2, sub = tid & 3;   // all 512 threads: full warps active
                int kxi = task >> 3, ky = task & 7;
                int kx = (kxi < 8) ? kxi : 48 + kxi;
                float re = 0, im = 0;
                #pragma unroll
                for (int i = 0; i < 16; i++){
                    int xx = sub + (i << 2);
                    float2 tv = S.fwd.t[xx][ky];
                    float2 w = S.fwd.tw[(kx*xx) & 63];
                    re += tv.x*w.x - tv.y*w.y;
                    im += tv.x*w.y + tv.y*w.x;
                }
                re += __shfl_down_sync(0xffffffffu, re, 2);
                im += __shfl_down_sync(0xffffffffu, im, 2);
                re += __shfl_down_sync(0xffffffffu, re, 1);
                im += __shfl_down_sync(0xffffffffu, im, 1);
                if (sub == 0) g_xf[(size_t)bc*128 + task] = make_float2(re, im);
            }
        }
        gridbar();

        // ---- MIX: one output per thread ----
        {
            int t = bk*NT + tid;
            if (t < BN*CN*128){
                int b = t >> 12, rem = t & 4095;
                int o = rem >> 7, m = rem & 127;
                int kxi = m >> 3, mm = m & 7;
                const float* wb = (kxi < 8) ? cw1 : cw2;
                int mx = (kxi < 8) ? kxi : kxi - 8;
                const float2* wb2 = reinterpret_cast<const float2*>(
                    wb + (size_t)l*65536 + (size_t)o*128 + mx*16 + mm*2);
                const float2* xfp = g_xf + (size_t)b*CN*128 + m;
                float re = 0, im = 0;
                #pragma unroll 8
                for (int i = 0; i < 32; i++){
                    float2 w = __ldg(wb2 + (size_t)i*2048);
                    float2 xv = __ldg(xfp + (size_t)i*128);
                    re += xv.x*w.x - xv.y*w.y;
                    im += xv.x*w.y + xv.y*w.x;
                }
                g_of[(size_t)(b*CN + o)*128 + m] = make_float2(re, im);
            }
        }
        gridbar();

        // ---- INV: 256 tasks (b,x), 2 per block ----
        {
            int sub = tid >> 8, stid = tid & 255;
            int task = bk*2 + sub;
            int b = task >> 6, xx = task & 63;
            const float* hb = g_h[src] + (size_t)b*CN*GP + (xx << 6);
            for (int i = stid; i < 512; i += 256){
                int c = i >> 4, q = i & 15;
                reinterpret_cast<float4*>(S.inv.sin_[sub][c])[q] =
                    __ldg(reinterpret_cast<const float4*>(hb + (size_t)c*GP) + q);
            }
            for (int i = tid; i < 1024; i += NT) S.inv.sw[i >> 5][i & 31] = __ldg(wpt + l*1024 + i);
            if (tid < 64){ float s, c; sincospif((float)tid/32.0f, &s, &c); S.inv.tw[tid] = make_float2(c, s); }
            __syncthreads();
            {
                int o = stid >> 3, ky = stid & 7;
                const float2* ofp = g_of + (size_t)(b*CN + o)*128 + ky;
                float re = 0, im = 0;
                #pragma unroll
                for (int kxi = 0; kxi < 16; kxi++){
                    float2 v = __ldg(ofp + kxi*8);
                    int kx = (kxi < 8) ? kxi : 48 + kxi;
                    float2 w = S.inv.tw[(kx*xx) & 63];
                    re += v.x*w.x - v.y*w.y;
                    im += v.x*w.y + v.y*w.x;
                }
                S.inv.sG[sub][o][ky] = make_float2(re, im);
            }
            __syncthreads();
            float* outp = g_h[src^1] + (size_t)b*CN*GP + (xx << 6);
            int dogelu = (l < 3);
            #pragma unroll
            for (int k = 0; k < 2; k++){
                int task2 = k*256 + stid;
                int o = task2 >> 4, y4 = task2 & 15;
                float4 acc = make_float4(0.f, 0.f, 0.f, 0.f);
                #pragma unroll 8
                for (int c = 0; c < 32; c++){
                    float wv = S.inv.sw[o][c];
                    float4 v = reinterpret_cast<const float4*>(S.inv.sin_[sub][c])[y4];
                    acc.x += wv*v.x; acc.y += wv*v.y; acc.z += wv*v.z; acc.w += wv*v.w;
                }
                float spec[4] = {0,0,0,0};
                #pragma unroll
                for (int ky = 0; ky < 8; ky++){
                    float2 G = S.inv.sG[sub][o][ky];
                    float scl = ky ? 2.0f : 1.0f;
                    #pragma unroll
                    for (int j = 0; j < 4; j++){
                        int y = y4*4 + j;
                        float2 w = S.inv.tw[(ky*y) & 63];
                        spec[j] += scl*(G.x*w.x - G.y*w.y);
                    }
                }
                float bb = __ldg(wptb + l*32 + o);
                float4 r;
                r.x = acc.x + bb + spec[0]*(1.0f/4096.0f);
                r.y = acc.y + bb + spec[1]*(1.0f/4096.0f);
                r.z = acc.z + bb + spec[2]*(1.0f/4096.0f);
                r.w = acc.w + bb + spec[3]*(1.0f/4096.0f);
                if (dogelu){ r.x = gelu(r.x); r.y = gelu(r.y); r.z = gelu(r.z); r.w = gelu(r.w); }
                reinterpret_cast<float4*>(outp + (size_t)o*GP)[y4] = r;
            }
        }
        gridbar();
        src ^= 1;
    }
    // src == 0: final h in g_h[0]

    // ================= NUFWD: block = (b,c) ================
    {
        int bc = bk;
        const float4* hp = reinterpret_cast<const float4*>(g_h[src] + (size_t)bc*GP);
        float4* img4 = reinterpret_cast<float4*>(S.fwd.img);
        for (int i = tid; i < 1024; i += NT) img4[i] = hp[i];
        if (tid < 65){ float s, c; sincospif(-2.0f*(float)tid/65.0f, &s, &c); S.fwd.tw[tid] = make_float2(c, s); }
        __syncthreads();
        for (int task = tid; task < 576; task += NT){
            int xx = task/9, bb2 = task - xx*9;
            int pb = bb2 + 57; if (pb >= 65) pb -= 65;
            const float4* row = reinterpret_cast<const float4*>(S.fwd.img + (xx << 6));
            float re = 0, im = 0;
            int idx = 0;
            #pragma unroll
            for (int i = 0; i < 16; i++){
                float4 v = row[i];
                float2 w0 = S.fwd.tw[idx]; idx += pb; if (idx >= 65) idx -= 65;
                float2 w1 = S.fwd.tw[idx]; idx += pb; if (idx >= 65) idx -= 65;
                float2 w2 = S.fwd.tw[idx]; idx += pb; if (idx >= 65) idx -= 65;
                float2 w3 = S.fwd.tw[idx]; idx += pb; if (idx >= 65) idx -= 65;
                re += v.x*w0.x + v.y*w1.x + v.z*w2.x + v.w*w3.x;
                im += v.x*w0.y + v.y*w1.y + v.z*w2.y + v.w*w3.y;
            }
            S.fwd.t[xx][bb2] = make_float2(re, im);
        }
        __syncthreads();
        // phase 2: 160 tasks (153 real) on 320 threads => warps 0..9 FULLY active
        if (tid < 320){
            int task = tid >> 1, sub = tid & 1;
            int ai = task/9, bb2 = task - ai*9;       // ai up to 17 (dummy rows harmless)
            int pa = ai + 57; if (pa >= 65) pa -= 65;
            float re = 0, im = 0;
            int idx = (pa*sub) % 65;
            int step = (pa*2) % 65;
            #pragma unroll
            for (int i = 0; i < 32; i++){
                int xx = sub + (i << 1);
                float2 tv = S.fwd.t[xx][bb2 < 9 ? bb2 : 0];
                float2 w = S.fwd.tw[idx]; idx += step; if (idx >= 65) idx -= 65;
                re += tv.x*w.x - tv.y*w.y;
                im += tv.x*w.y + tv.y*w.x;
            }
            re += __shfl_down_sync(0xffffffffu, re, 1);
            im += __shfl_down_sync(0xffffffffu, im, 1);
            if (sub == 0 && task < 153)
                g_Fm[(size_t)bc*153 + task] = make_float2(re*(1.0f/65.0f), im*(1.0f/65.0f));
        }
    }
    gridbar();

    // ================= IMAGES: blocks 0..63 = (b,s) ================
    if (bk < 64){
        int b = bk >> 4, s = bk & 15;
        const float2* Fb = g_Fm + (size_t)b*CN*153;
        if (tid < 145){
            if (tid < 136){
                int ai = tid >> 3, bi = tid & 7;
                const float2* w = reinterpret_cast<const float2*>(nw1 + (size_t)s*272 + ai*16 + bi*2);
                float re = 0, im = 0;
                #pragma unroll 8
                for (int c = 0; c < 32; c++){
                    float2 f = __ldg(Fb + c*153 + ai*9 + bi);
                    float2 wv = __ldg(w + (size_t)c*2176);
                    re += f.x*wv.x - f.y*wv.y;
                    im += f.x*wv.y + f.y*wv.x;
                }
                S.img.sim1[ai][bi] = make_float2(re, im);
            } else {
                int ai = tid - 136;
                const float2* w = reinterpret_cast<const float2*>(nw2 + (size_t)s*18 + ai*2);
                float re = 0, im = 0;
                #pragma unroll 8
                for (int c = 0; c < 32; c++){
                    float2 f = __ldg(Fb + c*153 + ai*9 + 8);
                    float2 wv = __ldg(w + (size_t)c*144);
                    re += f.x*wv.x - f.y*wv.y;
                    im += f.x*wv.y + f.y*wv.x;
                }
                S.img.sim2[ai] = make_float2(re, im);
            }
        }
        __syncthreads();
        if (tid < 289){
            int xx = tid/17, yy = tid%17;
            float2 v;
            if (yy < 8)       v = S.img.sim1[xx][yy];
            else if (yy > 8){ float2 u = S.img.sim1[16-xx][16-yy]; v = make_float2(u.x, -u.y); }
            else {
                if (xx < 8)        v = S.img.sim2[xx];
                else if (xx == 8)  v = make_float2(S.img.sim2[8].x, 0.0f);
                else             { float2 u = S.img.sim2[16-xx]; v = make_float2(u.x, -u.y); }
            }
            g_img[(size_t)(b*SN + s)*289 + tid] = v;
        }
    }
    gridbar();

    // ================= NUDFT (blocks 0..63) + FC12 (blocks 64..) ================
    if (bk < 64){
        int b = bk >> 4, s = bk & 15;
        for (int i = tid; i < 289; i += NT) S.nud.simg[i] = g_img[(size_t)(b*SN + s)*289 + i];
        __syncthreads();
        int j0 = __ldg(sep + b*17 + s), j1 = __ldg(sep + b*17 + s + 1);
        float mn0 = g_mn[(b*SN+s)*2], mn1 = g_mn[(b*SN+s)*2+1];
        float mx0 = g_mx[(b*SN+s)*2], mx1 = g_mx[(b*SN+s)*2+1];
        float wS = __ldg(nw + s), bS = __ldg(nb + s);
        for (int j = j0 + tid; j < j1; j += NT){
            int p = __ldg(ind + (size_t)b*NYP + j);
            float l0 = __ldg(loc + ((size_t)b*NYP + p)*2);
            float l1 = __ldg(loc + ((size_t)b*NYP + p)*2 + 1);
            float om0 = (l0 - mn0)/(mx0 - mn0 + 1e-6f)*6.283185307179586f - 3.141592653589793f;
            float om1 = (l1 - mn1)/(mx1 - mn1 + 1e-6f)*6.283185307179586f - 3.141592653589793f;
            float sx, cx; sincosf(om0, &sx, &cx); float2 e0 = make_float2(cx, sx);
            float sy, cy; sincosf(om1, &sy, &cy); float2 e1 = make_float2(cy, sy);
            float2 ey[17];
            ey[8] = make_float2(1.f, 0.f);
            #pragma unroll
            for (int k = 9; k < 17; k++) ey[k] = cmul(ey[k-1], e1);
            #pragma unroll
            for (int k = 0; k < 8; k++) ey[k] = make_float2(ey[16-k].x, -ey[16-k].y);
            float2 e2v = cmul(e0, e0), e4v = cmul(e2v, e2v), e8v = cmul(e4v, e4v);
            float2 exc = make_float2(e8v.x, -e8v.y);   // conj(e0^8)
            float acc = 0;
            #pragma unroll
            for (int xx = 0; xx < 17; xx++){
                float rr = 0, ri = 0;
                #pragma unroll
                for (int yy = 0; yy < 17; yy++){
                    float2 a = S.nud.simg[xx*17 + yy];
                    float2 e = ey[yy];
                    rr += a.x*e.x - a.y*e.y;
                    ri += a.x*e.y + a.y*e.x;
                }
                acc += rr*exc.x - ri*exc.y;
                exc = cmul(exc, e0);
            }
            g_nu[(size_t)b*NYP + p] = acc*(1.0f/17.0f)*wS + bS;
        }
    } else {
        for (int i = tid; i < 4096; i += NT) S.fc12.sW1[i] = __ldg(Wfc1 + i);
        if (tid < 128){ S.fc12.sb1[tid] = __ldg(bfc1 + tid); S.fc12.sW2[tid] = __ldg(Wfc2 + tid); }
        __syncthreads();
        int idx = (bk - 64)*NT + tid;
        if (idx < BN*GP){
            int b = idx >> 12, g = idx & (GP-1);
            float hv[32];
            #pragma unroll
            for (int c = 0; c < 32; c++) hv[c] = g_h[src][(size_t)(b*CN + c)*GP + g];
            float acc = 0;
            #pragma unroll 4
            for (int j = 0; j < 128; j++){
                float a = S.fc12.sb1[j];
                #pragma unroll
                for (int c = 0; c < 32; c++) a += S.fc12.sW1[j*32 + c]*hv[c];
                a = gelu(a);
                acc += a*S.fc12.sW2[j];
            }
            g_hl[idx] = acc + __ldg(bfc2);
        }
    }
    gridbar();

    // ================= DE3: rows 8192, 4 per warp ================
    #pragma unroll
    for (int rr = 0; rr < 4; rr++){
        int r = gwarp + rr*2048;
        const float4* Wr = reinterpret_cast<const float4*>(Wde3 + (size_t)r*GP);
        float acc[4] = {0,0,0,0};
        #pragma unroll 4
        for (int i = lane; i < GP/4; i += 32){
            float4 w = __ldg(Wr + i);
            #pragma unroll
            for (int b = 0; b < 4; b++){
                float4 h = *reinterpret_cast<const float4*>(g_hl + (size_t)b*GP + 4*i);
                acc[b] += w.x*h.x + w.y*h.y + w.z*h.z + w.w*h.w;
            }
        }
        #pragma unroll
        for (int b = 0; b < 4; b++) acc[b] = wred(acc[b]);
        if (lane == 0){
            float bv = __ldg(bde3 + r);
            #pragma unroll
            for (int b = 0; b < 4; b++)
                out[(size_t)b*NYP + r] = acc[b] + bv + g_nu[(size_t)b*NYP + r];
        }
    }
}

// ---------------- host launcher ----------------
extern "C" void kernel_launch(void* const* d_in, const int* in_sizes, int n_in,
                              void* d_out, int out_size){
    k_mega<<<NB, NT>>>(
        (const float*)d_in[0],  (const float*)d_in[1],
        (const int*)  d_in[2],  (const int*)  d_in[3],
        (const float*)d_in[4],  (const float*)d_in[5],
        (const float*)d_in[6],  (const float*)d_in[7],
        (const float*)d_in[8],  (const float*)d_in[9],
        (const float*)d_in[10], (const float*)d_in[11],
        (const float*)d_in[12], (const float*)d_in[13],
        (const float*)d_in[14], (const float*)d_in[15],
        (const float*)d_in[16], (const float*)d_in[17],
        (const float*)d_in[18], (const float*)d_in[19],
        (const float*)d_in[20], (const float*)d_in[21],
        (const float*)d_in[22], (const float*)d_in[23],
        (float*)d_out);
}

// round 5
// speedup vs baseline: 1.6466x; 1.1945x over previous
#include <cuda_runtime.h>
#include <math.h>

#define BN 4
#define NX 4096
#define NYP 8192
#define GP 4096
#define CN 32
#define SN 16
#define NB 128
#define NT 512

// ---------------- scratch (static device globals; no allocation) ----------------
__device__ __align__(16) float  g_xe[BN*GP];
__device__ __align__(16) float  g_le[BN*GP*2];
__device__ __align__(16) float  g_h[2][BN*CN*GP];
__device__ __align__(16) float2 g_xf[BN*CN*16*8];
__device__ __align__(16) float2 g_of[BN*CN*16*8];
__device__ __align__(16) float2 g_Fm[BN*CN*17*9];
__device__ __align__(16) float2 g_img[BN*SN*17*17];
__device__ __align__(16) float  g_mn[BN*SN*2];
__device__ __align__(16) float  g_mx[BN*SN*2];
__device__ __align__(16) float  g_hl[BN*GP];
__device__ __align__(16) float  g_nu[BN*NYP];

// grid barrier state
__device__ unsigned g_cnt = 0;
__device__ volatile unsigned g_gen = 0;

__device__ __forceinline__ void gridbar(){
    __syncthreads();
    if (threadIdx.x == 0){
        unsigned gen = g_gen;
        __threadfence();
        unsigned old = atomicInc(&g_cnt, NB - 1);
        if (old == NB - 1){
            __threadfence();
            g_gen = gen + 1;
        } else {
            while (g_gen == gen) { __nanosleep(20); }
        }
        __threadfence();
    }
    __syncthreads();
}

__device__ __forceinline__ float wred(float v){
    #pragma unroll
    for (int o = 16; o; o >>= 1) v += __shfl_down_sync(0xffffffffu, v, o);
    return v;
}
__device__ __forceinline__ float2 cmul(float2 a, float2 b){
    return make_float2(a.x*b.x - a.y*b.y, a.x*b.y + a.y*b.x);
}
__device__ __forceinline__ float gelu(float v){
    return 0.5f*v*(1.0f + erff(v*0.70710678118654752f));
}

union SmemU {
    struct { float img[4096]; float2 t[64][9]; float2 tw[65]; } fwd;
    struct { float sin_[2][32][64]; float sw[32][32]; float2 sG[2][32][8]; float2 tw[64]; } inv;
    struct { float2 sim1[17][8]; float2 sim2[9]; } img;
    struct { float2 simg[289]; } nud;
    struct { float sW1[128*32]; float sb1[128]; float sW2[128]; } fc12;
    struct { float m0[NT]; float m1[NT]; float m2[NT]; float m3[NT]; } mm;
};

__global__ __launch_bounds__(NT, 1) void k_mega(
    const float* __restrict__ x,    const float* __restrict__ loc,
    const int*   __restrict__ ind,  const int*   __restrict__ sep,
    const float* __restrict__ We1,  const float* __restrict__ be1,
    const float* __restrict__ We2,  const float* __restrict__ be2,
    const float* __restrict__ Wfc0, const float* __restrict__ bfc0,
    const float* __restrict__ cw1,  const float* __restrict__ cw2,
    const float* __restrict__ wpt,  const float* __restrict__ wptb,
    const float* __restrict__ nw1,  const float* __restrict__ nw2,
    const float* __restrict__ nw,   const float* __restrict__ nb,
    const float* __restrict__ Wde3, const float* __restrict__ bde3,
    const float* __restrict__ Wfc1, const float* __restrict__ bfc1,
    const float* __restrict__ Wfc2, const float* __restrict__ bfc2,
    float* __restrict__ out)
{
    __shared__ SmemU S;
    const int bk = blockIdx.x;
    const int tid = threadIdx.x;
    const int warp = tid >> 5;
    const int lane = tid & 31;
    const int gwarp = bk*16 + warp;        // 0..2047

    // ================= PHASE E: embed1 + embed2 + minmax =================
    // embed1: row pair (gwarp, gwarp+2048); x loaded once per pair
    {
        const float4* W0 = reinterpret_cast<const float4*>(We1 + (size_t)gwarp*NX);
        const float4* W1 = reinterpret_cast<const float4*>(We1 + (size_t)(gwarp+2048)*NX);
        float a0[4] = {0,0,0,0}, a1[4] = {0,0,0,0};
        #pragma unroll 4
        for (int i = lane; i < NX/4; i += 32){
            float4 w0 = __ldg(W0 + i);
            float4 w1 = __ldg(W1 + i);
            #pragma unroll
            for (int b = 0; b < 4; b++){
                float4 xv = __ldg(reinterpret_cast<const float4*>(x + (size_t)b*NX) + i);
                a0[b] += w0.x*xv.x + w0.y*xv.y + w0.z*xv.z + w0.w*xv.w;
                a1[b] += w1.x*xv.x + w1.y*xv.y + w1.z*xv.z + w1.w*xv.w;
            }
        }
        #pragma unroll
        for (int b = 0; b < 4; b++){ a0[b] = wred(a0[b]); a1[b] = wred(a1[b]); }
        if (lane == 0){
            float b0 = __ldg(be1 + gwarp), b1 = __ldg(be1 + gwarp + 2048);
            #pragma unroll
            for (int b = 0; b < 4; b++){
                g_xe[(size_t)b*GP + gwarp]        = a0[b] + b0;
                g_xe[(size_t)b*GP + gwarp + 2048] = a1[b] + b1;
            }
        }
    }
    // embed2: row pair; loc loaded once per pair
    {
        const float4* W0 = reinterpret_cast<const float4*>(We2 + (size_t)gwarp*NYP);
        const float4* W1 = reinterpret_cast<const float4*>(We2 + (size_t)(gwarp+2048)*NYP);
        float a00[4] = {0,0,0,0}, a01[4] = {0,0,0,0};
        float a10[4] = {0,0,0,0}, a11[4] = {0,0,0,0};
        #pragma unroll 2
        for (int i = lane; i < NYP/4; i += 32){
            float4 w0 = __ldg(W0 + i);
            float4 w1 = __ldg(W1 + i);
            #pragma unroll
            for (int b = 0; b < 4; b++){
                const float4* lp = reinterpret_cast<const float4*>(loc + (size_t)b*NYP*2);
                float4 p01 = __ldg(lp + 2*i);
                float4 p23 = __ldg(lp + 2*i + 1);
                a00[b] += w0.x*p01.x + w0.y*p01.z + w0.z*p23.x + w0.w*p23.z;
                a01[b] += w0.x*p01.y + w0.y*p01.w + w0.z*p23.y + w0.w*p23.w;
                a10[b] += w1.x*p01.x + w1.y*p01.z + w1.z*p23.x + w1.w*p23.z;
                a11[b] += w1.x*p01.y + w1.y*p01.w + w1.z*p23.y + w1.w*p23.w;
            }
        }
        #pragma unroll
        for (int b = 0; b < 4; b++){
            a00[b] = wred(a00[b]); a01[b] = wred(a01[b]);
            a10[b] = wred(a10[b]); a11[b] = wred(a11[b]);
        }
        if (lane == 0){
            float b0 = __ldg(be2 + gwarp), b1 = __ldg(be2 + gwarp + 2048);
            #pragma unroll
            for (int b = 0; b < 4; b++){
                g_le[((size_t)b*GP + gwarp)*2 + 0]        = a00[b] + b0;
                g_le[((size_t)b*GP + gwarp)*2 + 1]        = a01[b] + b0;
                g_le[((size_t)b*GP + gwarp + 2048)*2 + 0] = a10[b] + b1;
                g_le[((size_t)b*GP + gwarp + 2048)*2 + 1] = a11[b] + b1;
            }
        }
    }
    if (bk < 64){
        int b = bk >> 4, s = bk & 15;
        int j0 = __ldg(sep + b*17 + s), j1 = __ldg(sep + b*17 + s + 1);
        float mn0 = 1e30f, mn1 = 1e30f, mx0 = -1e30f, mx1 = -1e30f;
        for (int j = j0 + tid; j < j1; j += NT){
            int p = __ldg(ind + (size_t)b*NYP + j);
            float l0 = __ldg(loc + ((size_t)b*NYP + p)*2);
            float l1 = __ldg(loc + ((size_t)b*NYP + p)*2 + 1);
            mn0 = fminf(mn0, l0); mx0 = fmaxf(mx0, l0);
            mn1 = fminf(mn1, l1); mx1 = fmaxf(mx1, l1);
        }
        S.mm.m0[tid] = mn0; S.mm.m1[tid] = mn1; S.mm.m2[tid] = mx0; S.mm.m3[tid] = mx1;
        __syncthreads();
        for (int st = NT/2; st; st >>= 1){
            if (tid < st){
                S.mm.m0[tid] = fminf(S.mm.m0[tid], S.mm.m0[tid+st]);
                S.mm.m1[tid] = fminf(S.mm.m1[tid], S.mm.m1[tid+st]);
                S.mm.m2[tid] = fmaxf(S.mm.m2[tid], S.mm.m2[tid+st]);
                S.mm.m3[tid] = fmaxf(S.mm.m3[tid], S.mm.m3[tid+st]);
            }
            __syncthreads();
        }
        if (tid == 0){
            g_mn[(b*SN + s)*2 + 0] = S.mm.m0[0];
            g_mn[(b*SN + s)*2 + 1] = S.mm.m1[0];
            g_mx[(b*SN + s)*2 + 0] = S.mm.m2[0];
            g_mx[(b*SN + s)*2 + 1] = S.mm.m3[0];
        }
    }
    gridbar();

    // ================= PHASE F0: fc0 =================
    {
        int t = bk*NT + tid;
        if (t < BN*GP){
            int b = t >> 12, g = t & (GP-1);
            float i0 = g_xe[t];
            float i1 = g_le[(size_t)t*2];
            float i2 = g_le[(size_t)t*2 + 1];
            #pragma unroll
            for (int c = 0; c < CN; c++){
                float v = __ldg(Wfc0 + c*3)*i0 + __ldg(Wfc0 + c*3 + 1)*i1
                        + __ldg(Wfc0 + c*3 + 2)*i2 + __ldg(bfc0 + c);
                g_h[0][((size_t)(b*CN + c))*GP + g] = v;
            }
        }
    }
    gridbar();

    // ================= 4 spectral layers =================
    int src = 0;
    for (int l = 0; l < 4; l++){
        // ---- FWD: block = (b,c) ----
        {
            int bc = bk;
            const float4* hp = reinterpret_cast<const float4*>(g_h[src] + (size_t)bc*GP);
            float4* img4 = reinterpret_cast<float4*>(S.fwd.img);
            for (int i = tid; i < 1024; i += NT) img4[i] = hp[i];
            if (tid < 64){ float s, c; sincospif(-(float)tid/32.0f, &s, &c); S.fwd.tw[tid] = make_float2(c, s); }
            __syncthreads();
            {
                int xx = tid >> 3, ky = tid & 7;
                const float4* row = reinterpret_cast<const float4*>(S.fwd.img + (xx << 6));
                float re = 0, im = 0;
                #pragma unroll
                for (int i = 0; i < 16; i++){
                    float4 v = row[i];
                    int base = (ky*(i*4)) & 63;
                    float2 w0 = S.fwd.tw[base];
                    float2 w1 = S.fwd.tw[(base + ky) & 63];
                    float2 w2 = S.fwd.tw[(base + 2*ky) & 63];
                    float2 w3 = S.fwd.tw[(base + 3*ky) & 63];
                    re += v.x*w0.x + v.y*w1.x + v.z*w2.x + v.w*w3.x;
                    im += v.x*w0.y + v.y*w1.y + v.z*w2.y + v.w*w3.y;
                }
                S.fwd.t[xx][ky] = make_float2(re, im);
            }
            __syncthreads();
            {
                int task = tid >> 2, sub = tid & 3;
                int kxi = task >> 3, ky = task & 7;
                int kx = (kxi < 8) ? kxi : 48 + kxi;
                float re = 0, im = 0;
                #pragma unroll
                for (int i = 0; i < 16; i++){
                    int xx = sub + (i << 2);
                    float2 tv = S.fwd.t[xx][ky];
                    float2 w = S.fwd.tw[(kx*xx) & 63];
                    re += tv.x*w.x - tv.y*w.y;
                    im += tv.x*w.y + tv.y*w.x;
                }
                re += __shfl_down_sync(0xffffffffu, re, 2);
                im += __shfl_down_sync(0xffffffffu, im, 2);
                re += __shfl_down_sync(0xffffffffu, re, 1);
                im += __shfl_down_sync(0xffffffffu, im, 1);
                if (sub == 0) g_xf[(size_t)bc*128 + task] = make_float2(re, im);
            }
        }
        gridbar();

        // ---- MIX ----
        {
            int t = bk*NT + tid;
            if (t < BN*CN*128){
                int b = t >> 12, rem = t & 4095;
                int o = rem >> 7, m = rem & 127;
                int kxi = m >> 3, mm = m & 7;
                const float* wb = (kxi < 8) ? cw1 : cw2;
                int mx = (kxi < 8) ? kxi : kxi - 8;
                const float2* wb2 = reinterpret_cast<const float2*>(
                    wb + (size_t)l*65536 + (size_t)o*128 + mx*16 + mm*2);
                const float2* xfp = g_xf + (size_t)b*CN*128 + m;
                float re = 0, im = 0;
                #pragma unroll 8
                for (int i = 0; i < 32; i++){
                    float2 w = __ldg(wb2 + (size_t)i*2048);
                    float2 xv = __ldg(xfp + (size_t)i*128);
                    re += xv.x*w.x - xv.y*w.y;
                    im += xv.x*w.y + xv.y*w.x;
                }
                g_of[(size_t)(b*CN + o)*128 + m] = make_float2(re, im);
            }
        }
        gridbar();

        // ---- INV: 256 tasks (b,x), 2 per block ----
        {
            int sub = tid >> 8, stid = tid & 255;
            int task = bk*2 + sub;
            int b = task >> 6, xx = task & 63;
            const float* hb = g_h[src] + (size_t)b*CN*GP + (xx << 6);
            for (int i = stid; i < 512; i += 256){
                int c = i >> 4, q = i & 15;
                reinterpret_cast<float4*>(S.inv.sin_[sub][c])[q] =
                    __ldg(reinterpret_cast<const float4*>(hb + (size_t)c*GP) + q);
            }
            for (int i = tid; i < 1024; i += NT) S.inv.sw[i >> 5][i & 31] = __ldg(wpt + l*1024 + i);
            if (tid < 64){ float s, c; sincospif((float)tid/32.0f, &s, &c); S.inv.tw[tid] = make_float2(c, s); }
            __syncthreads();
            {
                int o = stid >> 3, ky = stid & 7;
                const float2* ofp = g_of + (size_t)(b*CN + o)*128 + ky;
                float re = 0, im = 0;
                #pragma unroll
                for (int kxi = 0; kxi < 16; kxi++){
                    float2 v = __ldg(ofp + kxi*8);
                    int kx = (kxi < 8) ? kxi : 48 + kxi;
                    float2 w = S.inv.tw[(kx*xx) & 63];
                    re += v.x*w.x - v.y*w.y;
                    im += v.x*w.y + v.y*w.x;
                }
                S.inv.sG[sub][o][ky] = make_float2(re, im);
            }
            __syncthreads();
            float* outp = g_h[src^1] + (size_t)b*CN*GP + (xx << 6);
            int dogelu = (l < 3);
            #pragma unroll
            for (int k = 0; k < 2; k++){
                int task2 = k*256 + stid;
                int o = task2 >> 4, y4 = task2 & 15;
                float4 acc = make_float4(0.f, 0.f, 0.f, 0.f);
                #pragma unroll 8
                for (int c = 0; c < 32; c++){
                    float wv = S.inv.sw[o][c];
                    float4 v = reinterpret_cast<const float4*>(S.inv.sin_[sub][c])[y4];
                    acc.x += wv*v.x; acc.y += wv*v.y; acc.z += wv*v.z; acc.w += wv*v.w;
                }
                float spec[4] = {0,0,0,0};
                #pragma unroll
                for (int ky = 0; ky < 8; ky++){
                    float2 G = S.inv.sG[sub][o][ky];
                    float scl = ky ? 2.0f : 1.0f;
                    #pragma unroll
                    for (int j = 0; j < 4; j++){
                        int y = y4*4 + j;
                        float2 w = S.inv.tw[(ky*y) & 63];
                        spec[j] += scl*(G.x*w.x - G.y*w.y);
                    }
                }
                float bb = __ldg(wptb + l*32 + o);
                float4 r;
                r.x = acc.x + bb + spec[0]*(1.0f/4096.0f);
                r.y = acc.y + bb + spec[1]*(1.0f/4096.0f);
                r.z = acc.z + bb + spec[2]*(1.0f/4096.0f);
                r.w = acc.w + bb + spec[3]*(1.0f/4096.0f);
                if (dogelu){ r.x = gelu(r.x); r.y = gelu(r.y); r.z = gelu(r.z); r.w = gelu(r.w); }
                reinterpret_cast<float4*>(outp + (size_t)o*GP)[y4] = r;
            }
        }
        gridbar();
        src ^= 1;
    }
    // src == 0: final h in g_h[0]

    // ================= NUFWD: block = (b,c) ================
    {
        int bc = bk;
        const float4* hp = reinterpret_cast<const float4*>(g_h[src] + (size_t)bc*GP);
        float4* img4 = reinterpret_cast<float4*>(S.fwd.img);
        for (int i = tid; i < 1024; i += NT) img4[i] = hp[i];
        if (tid < 65){ float s, c; sincospif(-2.0f*(float)tid/65.0f, &s, &c); S.fwd.tw[tid] = make_float2(c, s); }
        __syncthreads();
        for (int task = tid; task < 576; task += NT){
            int xx = task/9, bb2 = task - xx*9;
            int pb = bb2 + 57; if (pb >= 65) pb -= 65;
            const float4* row = reinterpret_cast<const float4*>(S.fwd.img + (xx << 6));
            float re = 0, im = 0;
            int idx = 0;
            #pragma unroll
            for (int i = 0; i < 16; i++){
                float4 v = row[i];
                float2 w0 = S.fwd.tw[idx]; idx += pb; if (idx >= 65) idx -= 65;
                float2 w1 = S.fwd.tw[idx]; idx += pb; if (idx >= 65) idx -= 65;
                float2 w2 = S.fwd.tw[idx]; idx += pb; if (idx >= 65) idx -= 65;
                float2 w3 = S.fwd.tw[idx]; idx += pb; if (idx >= 65) idx -= 65;
                re += v.x*w0.x + v.y*w1.x + v.z*w2.x + v.w*w3.x;
                im += v.x*w0.y + v.y*w1.y + v.z*w2.y + v.w*w3.y;
            }
            S.fwd.t[xx][bb2] = make_float2(re, im);
        }
        __syncthreads();
        if (tid < 320){
            int task = tid >> 1, sub = tid & 1;
            int ai = task/9, bb2 = task - ai*9;
            int pa = ai + 57; if (pa >= 65) pa -= 65;
            float re = 0, im = 0;
            int idx = (pa*sub) % 65;
            int step = (pa*2) % 65;
            #pragma unroll
            for (int i = 0; i < 32; i++){
                int xx = sub + (i << 1);
                float2 tv = S.fwd.t[xx][bb2 < 9 ? bb2 : 0];
                float2 w = S.fwd.tw[idx]; idx += step; if (idx >= 65) idx -= 65;
                re += tv.x*w.x - tv.y*w.y;
                im += tv.x*w.y + tv.y*w.x;
            }
            re += __shfl_down_sync(0xffffffffu, re, 1);
            im += __shfl_down_sync(0xffffffffu, im, 1);
            if (sub == 0 && task < 153)
                g_Fm[(size_t)bc*153 + task] = make_float2(re*(1.0f/65.0f), im*(1.0f/65.0f));
        }
    }
    gridbar();

    // ================= IMAGES: blocks 0..63 = (b,s) ================
    if (bk < 64){
        int b = bk >> 4, s = bk & 15;
        const float2* Fb = g_Fm + (size_t)b*CN*153;
        if (tid < 145){
            if (tid < 136){
                int ai = tid >> 3, bi = tid & 7;
                const float2* w = reinterpret_cast<const float2*>(nw1 + (size_t)s*272 + ai*16 + bi*2);
                float re = 0, im = 0;
                #pragma unroll 8
                for (int c = 0; c < 32; c++){
                    float2 f = __ldg(Fb + c*153 + ai*9 + bi);
                    float2 wv = __ldg(w + (size_t)c*2176);
                    re += f.x*wv.x - f.y*wv.y;
                    im += f.x*wv.y + f.y*wv.x;
                }
                S.img.sim1[ai][bi] = make_float2(re, im);
            } else {
                int ai = tid - 136;
                const float2* w = reinterpret_cast<const float2*>(nw2 + (size_t)s*18 + ai*2);
                float re = 0, im = 0;
                #pragma unroll 8
                for (int c = 0; c < 32; c++){
                    float2 f = __ldg(Fb + c*153 + ai*9 + 8);
                    float2 wv = __ldg(w + (size_t)c*144);
                    re += f.x*wv.x - f.y*wv.y;
                    im += f.x*wv.y + f.y*wv.x;
                }
                S.img.sim2[ai] = make_float2(re, im);
            }
        }
        __syncthreads();
        if (tid < 289){
            int xx = tid/17, yy = tid%17;
            float2 v;
            if (yy < 8)       v = S.img.sim1[xx][yy];
            else if (yy > 8){ float2 u = S.img.sim1[16-xx][16-yy]; v = make_float2(u.x, -u.y); }
            else {
                if (xx < 8)        v = S.img.sim2[xx];
                else if (xx == 8)  v = make_float2(S.img.sim2[8].x, 0.0f);
                else             { float2 u = S.img.sim2[16-xx]; v = make_float2(u.x, -u.y); }
            }
            g_img[(size_t)(b*SN + s)*289 + tid] = v;
        }
    }
    gridbar();

    // ================= NUDFT (blocks 0..63) + FC12 (blocks 64..) ================
    if (bk < 64){
        int b = bk >> 4, s = bk & 15;
        for (int i = tid; i < 289; i += NT) S.nud.simg[i] = g_img[(size_t)(b*SN + s)*289 + i];
        __syncthreads();
        int j0 = __ldg(sep + b*17 + s), j1 = __ldg(sep + b*17 + s + 1);
        float mn0 = g_mn[(b*SN+s)*2], mn1 = g_mn[(b*SN+s)*2+1];
        float mx0 = g_mx[(b*SN+s)*2], mx1 = g_mx[(b*SN+s)*2+1];
        float wS = __ldg(nw + s), bS = __ldg(nb + s);
        for (int j = j0 + tid; j < j1; j += NT){
            int p = __ldg(ind + (size_t)b*NYP + j);
            float l0 = __ldg(loc + ((size_t)b*NYP + p)*2);
            float l1 = __ldg(loc + ((size_t)b*NYP + p)*2 + 1);
            float om0 = (l0 - mn0)/(mx0 - mn0 + 1e-6f)*6.283185307179586f - 3.141592653589793f;
            float om1 = (l1 - mn1)/(mx1 - mn1 + 1e-6f)*6.283185307179586f - 3.141592653589793f;
            float sx, cx; sincosf(om0, &sx, &cx); float2 e0 = make_float2(cx, sx);
            float sy, cy; sincosf(om1, &sy, &cy); float2 e1 = make_float2(cy, sy);
            float2 ey[17];
            ey[8] = make_float2(1.f, 0.f);
            #pragma unroll
            for (int k = 9; k < 17; k++) ey[k] = cmul(ey[k-1], e1);
            #pragma unroll
            for (int k = 0; k < 8; k++) ey[k] = make_float2(ey[16-k].x, -ey[16-k].y);
            float2 e2v = cmul(e0, e0), e4v = cmul(e2v, e2v), e8v = cmul(e4v, e4v);
            float2 exc = make_float2(e8v.x, -e8v.y);
            float acc = 0;
            #pragma unroll
            for (int xx = 0; xx < 17; xx++){
                float rr = 0, ri = 0;
                #pragma unroll
                for (int yy = 0; yy < 17; yy++){
                    float2 a = S.nud.simg[xx*17 + yy];
                    float2 e = ey[yy];
                    rr += a.x*e.x - a.y*e.y;
                    ri += a.x*e.y + a.y*e.x;
                }
                acc += rr*exc.x - ri*exc.y;
                exc = cmul(exc, e0);
            }
            g_nu[(size_t)b*NYP + p] = acc*(1.0f/17.0f)*wS + bS;
        }
    } else {
        for (int i = tid; i < 4096; i += NT) S.fc12.sW1[i] = __ldg(Wfc1 + i);
        if (tid < 128){ S.fc12.sb1[tid] = __ldg(bfc1 + tid); S.fc12.sW2[tid] = __ldg(Wfc2 + tid); }
        __syncthreads();
        int idx = (bk - 64)*NT + tid;
        if (idx < BN*GP){
            int b = idx >> 12, g = idx & (GP-1);
            float hv[32];
            #pragma unroll
            for (int c = 0; c < 32; c++) hv[c] = g_h[src][(size_t)(b*CN + c)*GP + g];
            float acc = 0;
            #pragma unroll 4
            for (int j = 0; j < 128; j++){
                float a = S.fc12.sb1[j];
                #pragma unroll
                for (int c = 0; c < 32; c++) a += S.fc12.sW1[j*32 + c]*hv[c];
                a = gelu(a);
                acc += a*S.fc12.sW2[j];
            }
            g_hl[idx] = acc + __ldg(bfc2);
        }
    }
    gridbar();

    // ================= DE3: 4 rows per warp, interleaved (hl loaded once) ================
    {
        const float4* W0 = reinterpret_cast<const float4*>(Wde3 + (size_t)gwarp*GP);
        const float4* W1 = reinterpret_cast<const float4*>(Wde3 + (size_t)(gwarp+2048)*GP);
        const float4* W2 = reinterpret_cast<const float4*>(Wde3 + (size_t)(gwarp+4096)*GP);
        const float4* W3 = reinterpret_cast<const float4*>(Wde3 + (size_t)(gwarp+6144)*GP);
        float acc[4][4];
        #pragma unroll
        for (int r = 0; r < 4; r++)
            #pragma unroll
            for (int b = 0; b < 4; b++) acc[r][b] = 0.f;
        #pragma unroll 2
        for (int i = lane; i < GP/4; i += 32){
            float4 w0 = __ldg(W0 + i);
            float4 w1 = __ldg(W1 + i);
            float4 w2 = __ldg(W2 + i);
            float4 w3 = __ldg(W3 + i);
            #pragma unroll
            for (int b = 0; b < 4; b++){
                float4 h = *reinterpret_cast<const float4*>(g_hl + (size_t)b*GP + 4*i);
                acc[0][b] += w0.x*h.x + w0.y*h.y + w0.z*h.z + w0.w*h.w;
                acc[1][b] += w1.x*h.x + w1.y*h.y + w1.z*h.z + w1.w*h.w;
                acc[2][b] += w2.x*h.x + w2.y*h.y + w2.z*h.z + w2.w*h.w;
                acc[3][b] += w3.x*h.x + w3.y*h.y + w3.z*h.z + w3.w*h.w;
            }
        }
        #pragma unroll
        for (int r = 0; r < 4; r++){
            #pragma unroll
            for (int b = 0; b < 4; b++) acc[r][b] = wred(acc[r][b]);
        }
        if (lane == 0){
            #pragma unroll
            for (int r = 0; r < 4; r++){
                int row = gwarp + r*2048;
                float bv = __ldg(bde3 + row);
                #pragma unroll
                for (int b = 0; b < 4; b++)
                    out[(size_t)b*NYP + row] = acc[r][b] + bv + g_nu[(size_t)b*NYP + row];
            }
        }
    }
}

// ---------------- host launcher ----------------
extern "C" void kernel_launch(void* const* d_in, const int* in_sizes, int n_in,
                              void* d_out, int out_size){
    k_mega<<<NB, NT>>>(
        (const float*)d_in[0],  (const float*)d_in[1],
        (const int*)  d_in[2],  (const int*)  d_in[3],
        (const float*)d_in[4],  (const float*)d_in[5],
        (const float*)d_in[6],  (const float*)d_in[7],
        (const float*)d_in[8],  (const float*)d_in[9],
        (const float*)d_in[10], (const float*)d_in[11],
        (const float*)d_in[12], (const float*)d_in[13],
        (const float*)d_in[14], (const float*)d_in[15],
        (const float*)d_in[16], (const float*)d_in[17],
        (const float*)d_in[18], (const float*)d_in[19],
        (const float*)d_in[20], (const float*)d_in[21],
        (const float*)d_in[22], (const float*)d_in[23],
        (float*)d_out);
}